// round 1
// baseline (speedup 1.0000x reference)
#include <cuda_runtime.h>
#include <cstdint>

// ---------------- problem constants ----------------
#define T_LEN 512
#define B_SZ  128
#define D_EMB 256
#define HDIM  256
#define G4    1024      // 4*HD
#define LABN  32
#define START_TAG 30
#define NEGV  (-10000.0f)

// ---------------- device scratch (static, no allocation) ----------------
__device__ float g_xf[T_LEN * B_SZ * G4];     // 268 MB
__device__ float g_xb[T_LEN * B_SZ * G4];     // 268 MB
__device__ float g_hf[T_LEN * B_SZ * HDIM];   // 67 MB
__device__ float g_hb[T_LEN * B_SZ * HDIM];   // 67 MB
__device__ float g_feats[T_LEN * B_SZ * LABN];
__device__ float g_WoT[512 * 32];
__device__ float g_Z[B_SZ];
__device__ float g_gold[B_SZ];
__device__ unsigned g_count[2];
__device__ volatile unsigned g_release[2];

// ---------------- helpers ----------------
__device__ __forceinline__ float sigf(float x) {
    return 1.0f / (1.0f + __expf(-x));
}
__device__ __forceinline__ float tnh(float x) {
    // tanh(x) = 2/(1+exp(-2x)) - 1 ; saturates correctly at +-1
    return 2.0f / (1.0f + __expf(-2.0f * x)) - 1.0f;
}

// ---------------- prep: reset barriers + transpose Wo ----------------
__global__ void prep_kernel(const float* __restrict__ Wo) {
    int tx = threadIdx.x;
    if (tx < 2) { g_count[tx] = 0; g_release[tx] = 0; }
    // g_WoT[k*32 + l] = Wo[l*512 + k]
    for (int i = tx; i < 512 * 32; i += blockDim.x) {
        int l = i & 31, k = i >> 5;
        g_WoT[i] = Wo[l * 512 + k];
    }
}

// ---------------- input projection: out[m][n] = emb[sent[m]] . W[n] + bias[n]
// M=65536, N=1024 (per direction), K=256.  128x128x8 SGEMM tiles, 8x8/thread.
__global__ void __launch_bounds__(256) proj_kernel(
    const float* __restrict__ emb, const int* __restrict__ sent,
    const float* __restrict__ Wf, const float* __restrict__ bf,
    const float* __restrict__ Wb, const float* __restrict__ bb)
{
    const int dir = blockIdx.z;
    const float* W    = dir ? Wb : Wf;
    const float* bias = dir ? bb : bf;
    float* out        = dir ? g_xb : g_xf;

    __shared__ float sA[8][128];
    __shared__ float sB[8][128];

    const int tx = threadIdx.x;
    const int m0 = blockIdx.x * 128;
    const int n0 = blockIdx.y * 128;

    const int row = tx >> 1;          // 0..127
    const int kq  = (tx & 1) * 4;     // 0 or 4
    const int erow = sent[m0 + row];
    const float* aptr = emb + (size_t)erow * 256 + kq;
    const float* bptr = W + (size_t)(n0 + row) * 256 + kq;

    const int tm = (tx >> 4) * 8;
    const int tn = (tx & 15) * 8;

    float acc[8][8];
#pragma unroll
    for (int i = 0; i < 8; i++)
#pragma unroll
        for (int j = 0; j < 8; j++) acc[i][j] = 0.0f;

    for (int kk = 0; kk < 256; kk += 8) {
        float4 a4 = *(const float4*)(aptr + kk);
        float4 b4 = *(const float4*)(bptr + kk);
        __syncthreads();
        sA[kq + 0][row] = a4.x; sA[kq + 1][row] = a4.y;
        sA[kq + 2][row] = a4.z; sA[kq + 3][row] = a4.w;
        sB[kq + 0][row] = b4.x; sB[kq + 1][row] = b4.y;
        sB[kq + 2][row] = b4.z; sB[kq + 3][row] = b4.w;
        __syncthreads();
#pragma unroll
        for (int k = 0; k < 8; k++) {
            float a[8], b[8];
            *(float4*)&a[0] = *(const float4*)&sA[k][tm];
            *(float4*)&a[4] = *(const float4*)&sA[k][tm + 4];
            *(float4*)&b[0] = *(const float4*)&sB[k][tn];
            *(float4*)&b[4] = *(const float4*)&sB[k][tn + 4];
#pragma unroll
            for (int i = 0; i < 8; i++)
#pragma unroll
                for (int j = 0; j < 8; j++)
                    acc[i][j] = fmaf(a[i], b[j], acc[i][j]);
        }
    }

    float bvec[8];
#pragma unroll
    for (int j = 0; j < 8; j++) bvec[j] = bias[n0 + tn + j];
#pragma unroll
    for (int i = 0; i < 8; i++) {
        const int m = m0 + tm + i;
        float* orow = out + (size_t)m * 1024 + n0 + tn;
#pragma unroll
        for (int j = 0; j < 8; j++) orow[j] = acc[i][j] + bvec[j];
    }
}

// ---------------- persistent bi-LSTM recurrence ----------------
// 128 CTAs: dir = bx>>6 ; per dir 64 CTAs = 8 batch-tiles(16) x 8 j-tiles(32)
// W_hh slice (128 rows x 256) in smem, layout sW[(k*32+jj)*4 + gate] so the
// 4 gate weights for (k,jj) load as one conflict-free LDS.128.
// c-state lives in registers across all 512 steps; h shared via global + spin barrier.
#define LSTM_SMEM ((32768 + 4096) * 4)

__global__ void __launch_bounds__(256, 1) lstm_kernel(
    const float* __restrict__ Whf, const float* __restrict__ Whb,
    const float* __restrict__ h0, const float* __restrict__ c0)
{
    extern __shared__ float smem[];
    float* sW = smem;           // 32768 floats
    float* sH = smem + 32768;   // 16 x 256

    const int tx  = threadIdx.x;
    const int bx  = blockIdx.x;
    const int dir = bx >> 6;
    const int cid = bx & 63;
    const int b0  = (cid >> 3) << 4;   // batch tile start (16 wide)
    const int j0  = (cid & 7) << 5;    // j tile start (32 wide)

    const float* W  = dir ? Whb : Whf;
    const float* xp = dir ? g_xb : g_xf;
    float* hout     = dir ? g_hb : g_hf;

    // load W_hh slice: rows {gate*256 + j0 + jj} for gate 0..3, jj 0..31
    if (tx < 128) {
        const int q = tx & 3, jjl = tx >> 2;
        const float* wr = W + (size_t)(q * 256 + j0 + jjl) * 256;
#pragma unroll 4
        for (int k = 0; k < 256; k += 4) {
            float4 w4 = *(const float4*)(wr + k);
            sW[((k + 0) * 32 + jjl) * 4 + q] = w4.x;
            sW[((k + 1) * 32 + jjl) * 4 + q] = w4.y;
            sW[((k + 2) * 32 + jjl) * 4 + q] = w4.z;
            sW[((k + 3) * 32 + jjl) * 4 + q] = w4.w;
        }
    }

    const int bg = tx >> 5;     // warp id 0..7 -> 2 batches each
    const int lj = tx & 31;     // jj within tile
    const int bA = b0 + bg * 2, bB = bA + 1;

    float cA = c0[(size_t)(dir * 128 + bA) * 256 + j0 + lj];
    float cB = c0[(size_t)(dir * 128 + bB) * 256 + j0 + lj];

    for (int i = tx; i < 4096; i += 256)
        sH[i] = h0[(size_t)(dir * 128 + b0) * 256 + i];
    __syncthreads();

    for (int s = 0; s < 512; s++) {
        const int t = dir ? (511 - s) : s;
        const float* xr = xp + (size_t)t * (B_SZ * G4);

        float accA[4], accB[4];
#pragma unroll
        for (int q = 0; q < 4; q++) {
            accA[q] = xr[bA * 1024 + q * 256 + j0 + lj];
            accB[q] = xr[bB * 1024 + q * 256 + j0 + lj];
        }

        const float* shA = sH + (bg * 2) * 256;
        const float* shB = shA + 256;
#pragma unroll 2
        for (int k = 0; k < 256; k += 4) {
            float4 hA4 = *(const float4*)(shA + k);
            float4 hB4 = *(const float4*)(shB + k);
            float4 w0 = *(const float4*)(sW + ((k + 0) * 32 + lj) * 4);
            float4 w1 = *(const float4*)(sW + ((k + 1) * 32 + lj) * 4);
            float4 w2 = *(const float4*)(sW + ((k + 2) * 32 + lj) * 4);
            float4 w3 = *(const float4*)(sW + ((k + 3) * 32 + lj) * 4);
            accA[0] = fmaf(w0.x, hA4.x, accA[0]);
            accA[1] = fmaf(w0.y, hA4.x, accA[1]);
            accA[2] = fmaf(w0.z, hA4.x, accA[2]);
            accA[3] = fmaf(w0.w, hA4.x, accA[3]);
            accB[0] = fmaf(w0.x, hB4.x, accB[0]);
            accB[1] = fmaf(w0.y, hB4.x, accB[1]);
            accB[2] = fmaf(w0.z, hB4.x, accB[2]);
            accB[3] = fmaf(w0.w, hB4.x, accB[3]);

            accA[0] = fmaf(w1.x, hA4.y, accA[0]);
            accA[1] = fmaf(w1.y, hA4.y, accA[1]);
            accA[2] = fmaf(w1.z, hA4.y, accA[2]);
            accA[3] = fmaf(w1.w, hA4.y, accA[3]);
            accB[0] = fmaf(w1.x, hB4.y, accB[0]);
            accB[1] = fmaf(w1.y, hB4.y, accB[1]);
            accB[2] = fmaf(w1.z, hB4.y, accB[2]);
            accB[3] = fmaf(w1.w, hB4.y, accB[3]);

            accA[0] = fmaf(w2.x, hA4.z, accA[0]);
            accA[1] = fmaf(w2.y, hA4.z, accA[1]);
            accA[2] = fmaf(w2.z, hA4.z, accA[2]);
            accA[3] = fmaf(w2.w, hA4.z, accA[3]);
            accB[0] = fmaf(w2.x, hB4.z, accB[0]);
            accB[1] = fmaf(w2.y, hB4.z, accB[1]);
            accB[2] = fmaf(w2.z, hB4.z, accB[2]);
            accB[3] = fmaf(w2.w, hB4.z, accB[3]);

            accA[0] = fmaf(w3.x, hA4.w, accA[0]);
            accA[1] = fmaf(w3.y, hA4.w, accA[1]);
            accA[2] = fmaf(w3.z, hA4.w, accA[2]);
            accA[3] = fmaf(w3.w, hA4.w, accA[3]);
            accB[0] = fmaf(w3.x, hB4.w, accB[0]);
            accB[1] = fmaf(w3.y, hB4.w, accB[1]);
            accB[2] = fmaf(w3.z, hB4.w, accB[2]);
            accB[3] = fmaf(w3.w, hB4.w, accB[3]);
        }

        // gates: i, f, g, o (torch order)
        float iA = sigf(accA[0]), fA = sigf(accA[1]);
        float gA = tnh(accA[2]),  oA = sigf(accA[3]);
        cA = fA * cA + iA * gA;
        float hAv = oA * tnh(cA);
        float iB = sigf(accB[0]), fB = sigf(accB[1]);
        float gB = tnh(accB[2]),  oB = sigf(accB[3]);
        cB = fB * cB + iB * gB;
        float hBv = oB * tnh(cB);

        hout[(size_t)(t * 128 + bA) * 256 + j0 + lj] = hAv;
        hout[(size_t)(t * 128 + bB) * 256 + j0 + lj] = hBv;

        // per-direction grid barrier (64 CTAs, monotonic gen counter)
        __syncthreads();
        if (tx == 0) {
            __threadfence();
            unsigned arrived = atomicAdd(&g_count[dir], 1u);
            if (arrived == 64u * (unsigned)(s + 1) - 1u) {
                __threadfence();
                g_release[dir] = (unsigned)(s + 1);
            } else {
                while (g_release[dir] < (unsigned)(s + 1)) __nanosleep(20);
            }
            __threadfence();
        }
        __syncthreads();

        if (s < 511) {
            const float* hsrc = hout + (size_t)(t * 128 + b0) * 256;
            for (int i = tx; i < 4096; i += 256) sH[i] = hsrc[i];
            __syncthreads();
        }
    }
}

// ---------------- feats = concat(hf,hb) @ Wo^T + bo ----------------
#define FEATS_SMEM (512 * 32 * 4)
__global__ void __launch_bounds__(256) feats_kernel(const float* __restrict__ bo)
{
    extern __shared__ float sWo[];  // [512][32]: sWo[k*32 + l]
    const int tx = threadIdx.x;
    for (int i = tx; i < 512 * 32; i += 256) sWo[i] = g_WoT[i];
    __syncthreads();

    const int w = tx >> 5, l = tx & 31;
    const int m0 = blockIdx.x * 64 + w * 8;
    const float bias = bo[l];

#pragma unroll 1
    for (int r = 0; r < 8; r++) {
        const int m = m0 + r;
        const float* hf = &g_hf[(size_t)m * 256];
        const float* hb = &g_hb[(size_t)m * 256];
        float acc = bias;
#pragma unroll 4
        for (int k = 0; k < 256; k += 4) {
            float4 h4 = *(const float4*)(hf + k);
            acc = fmaf(h4.x, sWo[(k + 0) * 32 + l], acc);
            acc = fmaf(h4.y, sWo[(k + 1) * 32 + l], acc);
            acc = fmaf(h4.z, sWo[(k + 2) * 32 + l], acc);
            acc = fmaf(h4.w, sWo[(k + 3) * 32 + l], acc);
        }
#pragma unroll 4
        for (int k = 0; k < 256; k += 4) {
            float4 h4 = *(const float4*)(hb + k);
            acc = fmaf(h4.x, sWo[(256 + k + 0) * 32 + l], acc);
            acc = fmaf(h4.y, sWo[(256 + k + 1) * 32 + l], acc);
            acc = fmaf(h4.z, sWo[(256 + k + 2) * 32 + l], acc);
            acc = fmaf(h4.w, sWo[(256 + k + 3) * 32 + l], acc);
        }
        g_feats[(size_t)m * 32 + l] = acc;
    }
}

// ---------------- CRF forward (log-partition): one warp per batch elem ----------------
__global__ void __launch_bounds__(32) crf_fwd_kernel(const float* __restrict__ trans)
{
    const int b = blockIdx.x;
    const int l = threadIdx.x;  // destination tag

    float tr[32];
#pragma unroll
    for (int i = 0; i < 32; i++) tr[i] = trans[i * 32 + l];  // trans[i][l]

    float dp = (l == START_TAG) ? 0.0f : NEGV;

    for (int t = 0; t < 512; t++) {
        float sc = g_feats[(size_t)(t * 128 + b) * 32 + l];
        float v[32];
        float m = -3.0e38f;
#pragma unroll
        for (int i = 0; i < 32; i++) {
            v[i] = __shfl_sync(0xffffffffu, dp, i) + tr[i];
            m = fmaxf(m, v[i]);
        }
        float ssum = 0.0f;
#pragma unroll
        for (int i = 0; i < 32; i++) ssum += __expf(v[i] - m);
        dp = m + __logf(ssum) + sc;
    }

    // logsumexp over lanes
    float m = dp;
#pragma unroll
    for (int o = 16; o; o >>= 1) m = fmaxf(m, __shfl_xor_sync(0xffffffffu, m, o));
    float e = __expf(dp - m);
#pragma unroll
    for (int o = 16; o; o >>= 1) e += __shfl_xor_sync(0xffffffffu, e, o);
    if (l == 0) g_Z[b] = m + __logf(e);
}

// ---------------- gold path score ----------------
__global__ void __launch_bounds__(128) gold_kernel(
    const int* __restrict__ labels, const float* __restrict__ trans)
{
    const int b = threadIdx.x;
    float g = 0.0f;
    int lp = START_TAG;
#pragma unroll 4
    for (int t = 0; t < 512; t++) {
        int ln = labels[t * 128 + b];
        g += trans[lp * 32 + ln] + g_feats[(size_t)(t * 128 + b) * 32 + ln];
        lp = ln;
    }
    g_gold[b] = g;
}

// ---------------- final reduce ----------------
__global__ void __launch_bounds__(128) final_kernel(float* __restrict__ out)
{
    __shared__ float red[128];
    const int b = threadIdx.x;
    red[b] = g_Z[b] - g_gold[b];
    __syncthreads();
    for (int o = 64; o; o >>= 1) {
        if (b < o) red[b] += red[b + o];
        __syncthreads();
    }
    if (b == 0) out[0] = red[0] / 128.0f;
}

// ---------------- launch ----------------
extern "C" void kernel_launch(void* const* d_in, const int* in_sizes, int n_in,
                              void* d_out, int out_size)
{
    (void)in_sizes; (void)n_in; (void)out_size;
    const float* emb    = (const float*)d_in[0];
    const float* W_ih_f = (const float*)d_in[1];
    const float* W_hh_f = (const float*)d_in[2];
    const float* b_f    = (const float*)d_in[3];
    const float* W_ih_b = (const float*)d_in[4];
    const float* W_hh_b = (const float*)d_in[5];
    const float* b_b    = (const float*)d_in[6];
    const float* Wo     = (const float*)d_in[7];
    const float* bo     = (const float*)d_in[8];
    const float* trans  = (const float*)d_in[9];
    const float* h0     = (const float*)d_in[10];
    const float* c0     = (const float*)d_in[11];
    const int*   sent   = (const int*)d_in[12];
    const int*   labels = (const int*)d_in[13];
    float* out = (float*)d_out;

    cudaFuncSetAttribute(lstm_kernel, cudaFuncAttributeMaxDynamicSharedMemorySize, LSTM_SMEM);
    cudaFuncSetAttribute(feats_kernel, cudaFuncAttributeMaxDynamicSharedMemorySize, FEATS_SMEM);

    prep_kernel<<<1, 256>>>(Wo);
    proj_kernel<<<dim3(512, 8, 2), 256>>>(emb, sent, W_ih_f, b_f, W_ih_b, b_b);
    lstm_kernel<<<128, 256, LSTM_SMEM>>>(W_hh_f, W_hh_b, h0, c0);
    feats_kernel<<<1024, 256, FEATS_SMEM>>>(bo);
    crf_fwd_kernel<<<128, 32>>>(trans);
    gold_kernel<<<1, 128>>>(labels, trans);
    final_kernel<<<1, 128>>>(out);
}

// round 2
// speedup vs baseline: 1.0073x; 1.0073x over previous
#include <cuda_runtime.h>
#include <cstdint>

// ---------------- problem constants ----------------
#define T_LEN 512
#define B_SZ  128
#define D_EMB 256
#define HDIM  256
#define G4    1024      // 4*HD
#define LABN  32
#define START_TAG 30
#define NEGV  (-10000.0f)

// ---------------- device scratch (static, no allocation) ----------------
__device__ float g_xf[T_LEN * B_SZ * G4];     // 268 MB
__device__ float g_xb[T_LEN * B_SZ * G4];     // 268 MB
__device__ float g_hf[T_LEN * B_SZ * HDIM];   // 67 MB
__device__ float g_hb[T_LEN * B_SZ * HDIM];   // 67 MB
__device__ float g_feats[T_LEN * B_SZ * LABN];
__device__ float g_WoT[512 * 32];
__device__ float g_Z[B_SZ];
__device__ float g_gold[B_SZ];
__device__ unsigned g_count[2];
__device__ volatile unsigned g_release[2];

// ---------------- helpers ----------------
__device__ __forceinline__ float sigf(float x) {
    return 1.0f / (1.0f + __expf(-x));
}
__device__ __forceinline__ float tnh(float x) {
    // tanh(x) = 2/(1+exp(-2x)) - 1 ; saturates correctly at +-1
    return 2.0f / (1.0f + __expf(-2.0f * x)) - 1.0f;
}

// ---------------- prep: reset barriers + transpose Wo ----------------
__global__ void prep_kernel(const float* __restrict__ Wo) {
    int tx = threadIdx.x;
    if (tx < 2) { g_count[tx] = 0; g_release[tx] = 0; }
    // g_WoT[k*32 + l] = Wo[l*512 + k]
    for (int i = tx; i < 512 * 32; i += blockDim.x) {
        int l = i & 31, k = i >> 5;
        g_WoT[i] = Wo[l * 512 + k];
    }
}

// ---------------- input projection: out[m][n] = emb[sent[m]] . W[n] + bias[n]
// M=65536, N=1024 (per direction), K=256.  128x128x8 SGEMM tiles, 8x8/thread.
__global__ void __launch_bounds__(256) proj_kernel(
    const float* __restrict__ emb, const int* __restrict__ sent,
    const float* __restrict__ Wf, const float* __restrict__ bf,
    const float* __restrict__ Wb, const float* __restrict__ bb)
{
    const int dir = blockIdx.z;
    const float* W    = dir ? Wb : Wf;
    const float* bias = dir ? bb : bf;
    float* out        = dir ? g_xb : g_xf;

    __shared__ float sA[8][128];
    __shared__ float sB[8][128];

    const int tx = threadIdx.x;
    const int m0 = blockIdx.x * 128;
    const int n0 = blockIdx.y * 128;

    const int row = tx >> 1;          // 0..127
    const int kq  = (tx & 1) * 4;     // 0 or 4
    const int erow = sent[m0 + row];
    const float* aptr = emb + (size_t)erow * 256 + kq;
    const float* bptr = W + (size_t)(n0 + row) * 256 + kq;

    const int tm = (tx >> 4) * 8;
    const int tn = (tx & 15) * 8;

    float acc[8][8];
#pragma unroll
    for (int i = 0; i < 8; i++)
#pragma unroll
        for (int j = 0; j < 8; j++) acc[i][j] = 0.0f;

    for (int kk = 0; kk < 256; kk += 8) {
        float4 a4 = *(const float4*)(aptr + kk);
        float4 b4 = *(const float4*)(bptr + kk);
        __syncthreads();
        sA[kq + 0][row] = a4.x; sA[kq + 1][row] = a4.y;
        sA[kq + 2][row] = a4.z; sA[kq + 3][row] = a4.w;
        sB[kq + 0][row] = b4.x; sB[kq + 1][row] = b4.y;
        sB[kq + 2][row] = b4.z; sB[kq + 3][row] = b4.w;
        __syncthreads();
#pragma unroll
        for (int k = 0; k < 8; k++) {
            float a[8], b[8];
            *(float4*)&a[0] = *(const float4*)&sA[k][tm];
            *(float4*)&a[4] = *(const float4*)&sA[k][tm + 4];
            *(float4*)&b[0] = *(const float4*)&sB[k][tn];
            *(float4*)&b[4] = *(const float4*)&sB[k][tn + 4];
#pragma unroll
            for (int i = 0; i < 8; i++)
#pragma unroll
                for (int j = 0; j < 8; j++)
                    acc[i][j] = fmaf(a[i], b[j], acc[i][j]);
        }
    }

    float bvec[8];
#pragma unroll
    for (int j = 0; j < 8; j++) bvec[j] = bias[n0 + tn + j];
#pragma unroll
    for (int i = 0; i < 8; i++) {
        const int m = m0 + tm + i;
        float* orow = out + (size_t)m * 1024 + n0 + tn;
#pragma unroll
        for (int j = 0; j < 8; j++) orow[j] = acc[i][j] + bvec[j];
    }
}

// ---------------- persistent bi-LSTM recurrence ----------------
// 128 CTAs: dir = bx>>6 ; per dir 64 CTAs = 8 batch-tiles(16) x 8 j-tiles(32)
// W_hh slice (128 rows x 256) in smem, layout sW[(k*32+jj)*4 + gate] so the
// 4 gate weights for (k,jj) load as one conflict-free LDS.128.
// c-state lives in registers across all 512 steps; h shared via global + spin barrier.
#define LSTM_SMEM ((32768 + 4096) * 4)

__global__ void __launch_bounds__(256, 1) lstm_kernel(
    const float* __restrict__ Whf, const float* __restrict__ Whb,
    const float* __restrict__ h0, const float* __restrict__ c0)
{
    extern __shared__ float smem[];
    float* sW = smem;           // 32768 floats
    float* sH = smem + 32768;   // 16 x 256

    const int tx  = threadIdx.x;
    const int bx  = blockIdx.x;
    const int dir = bx >> 6;
    const int cid = bx & 63;
    const int b0  = (cid >> 3) << 4;   // batch tile start (16 wide)
    const int j0  = (cid & 7) << 5;    // j tile start (32 wide)

    const float* W  = dir ? Whb : Whf;
    const float* xp = dir ? g_xb : g_xf;
    float* hout     = dir ? g_hb : g_hf;

    // load W_hh slice: rows {gate*256 + j0 + jj} for gate 0..3, jj 0..31
    if (tx < 128) {
        const int q = tx & 3, jjl = tx >> 2;
        const float* wr = W + (size_t)(q * 256 + j0 + jjl) * 256;
#pragma unroll 4
        for (int k = 0; k < 256; k += 4) {
            float4 w4 = *(const float4*)(wr + k);
            sW[((k + 0) * 32 + jjl) * 4 + q] = w4.x;
            sW[((k + 1) * 32 + jjl) * 4 + q] = w4.y;
            sW[((k + 2) * 32 + jjl) * 4 + q] = w4.z;
            sW[((k + 3) * 32 + jjl) * 4 + q] = w4.w;
        }
    }

    const int bg = tx >> 5;     // warp id 0..7 -> 2 batches each
    const int lj = tx & 31;     // jj within tile
    const int bA = b0 + bg * 2, bB = bA + 1;

    float cA = c0[(size_t)(dir * 128 + bA) * 256 + j0 + lj];
    float cB = c0[(size_t)(dir * 128 + bB) * 256 + j0 + lj];

    for (int i = tx; i < 4096; i += 256)
        sH[i] = h0[(size_t)(dir * 128 + b0) * 256 + i];
    __syncthreads();

    for (int s = 0; s < 512; s++) {
        const int t = dir ? (511 - s) : s;
        const float* xr = xp + (size_t)t * (B_SZ * G4);

        float accA[4], accB[4];
#pragma unroll
        for (int q = 0; q < 4; q++) {
            accA[q] = xr[bA * 1024 + q * 256 + j0 + lj];
            accB[q] = xr[bB * 1024 + q * 256 + j0 + lj];
        }

        const float* shA = sH + (bg * 2) * 256;
        const float* shB = shA + 256;
#pragma unroll 2
        for (int k = 0; k < 256; k += 4) {
            float4 hA4 = *(const float4*)(shA + k);
            float4 hB4 = *(const float4*)(shB + k);
            float4 w0 = *(const float4*)(sW + ((k + 0) * 32 + lj) * 4);
            float4 w1 = *(const float4*)(sW + ((k + 1) * 32 + lj) * 4);
            float4 w2 = *(const float4*)(sW + ((k + 2) * 32 + lj) * 4);
            float4 w3 = *(const float4*)(sW + ((k + 3) * 32 + lj) * 4);
            accA[0] = fmaf(w0.x, hA4.x, accA[0]);
            accA[1] = fmaf(w0.y, hA4.x, accA[1]);
            accA[2] = fmaf(w0.z, hA4.x, accA[2]);
            accA[3] = fmaf(w0.w, hA4.x, accA[3]);
            accB[0] = fmaf(w0.x, hB4.x, accB[0]);
            accB[1] = fmaf(w0.y, hB4.x, accB[1]);
            accB[2] = fmaf(w0.z, hB4.x, accB[2]);
            accB[3] = fmaf(w0.w, hB4.x, accB[3]);

            accA[0] = fmaf(w1.x, hA4.y, accA[0]);
            accA[1] = fmaf(w1.y, hA4.y, accA[1]);
            accA[2] = fmaf(w1.z, hA4.y, accA[2]);
            accA[3] = fmaf(w1.w, hA4.y, accA[3]);
            accB[0] = fmaf(w1.x, hB4.y, accB[0]);
            accB[1] = fmaf(w1.y, hB4.y, accB[1]);
            accB[2] = fmaf(w1.z, hB4.y, accB[2]);
            accB[3] = fmaf(w1.w, hB4.y, accB[3]);

            accA[0] = fmaf(w2.x, hA4.z, accA[0]);
            accA[1] = fmaf(w2.y, hA4.z, accA[1]);
            accA[2] = fmaf(w2.z, hA4.z, accA[2]);
            accA[3] = fmaf(w2.w, hA4.z, accA[3]);
            accB[0] = fmaf(w2.x, hB4.z, accB[0]);
            accB[1] = fmaf(w2.y, hB4.z, accB[1]);
            accB[2] = fmaf(w2.z, hB4.z, accB[2]);
            accB[3] = fmaf(w2.w, hB4.z, accB[3]);

            accA[0] = fmaf(w3.x, hA4.w, accA[0]);
            accA[1] = fmaf(w3.y, hA4.w, accA[1]);
            accA[2] = fmaf(w3.z, hA4.w, accA[2]);
            accA[3] = fmaf(w3.w, hA4.w, accA[3]);
            accB[0] = fmaf(w3.x, hB4.w, accB[0]);
            accB[1] = fmaf(w3.y, hB4.w, accB[1]);
            accB[2] = fmaf(w3.z, hB4.w, accB[2]);
            accB[3] = fmaf(w3.w, hB4.w, accB[3]);
        }

        // gates: i, f, g, o (torch order)
        float iA = sigf(accA[0]), fA = sigf(accA[1]);
        float gA = tnh(accA[2]),  oA = sigf(accA[3]);
        cA = fA * cA + iA * gA;
        float hAv = oA * tnh(cA);
        float iB = sigf(accB[0]), fB = sigf(accB[1]);
        float gB = tnh(accB[2]),  oB = sigf(accB[3]);
        cB = fB * cB + iB * gB;
        float hBv = oB * tnh(cB);

        hout[(size_t)(t * 128 + bA) * 256 + j0 + lj] = hAv;
        hout[(size_t)(t * 128 + bB) * 256 + j0 + lj] = hBv;

        // per-direction grid barrier (64 CTAs, monotonic gen counter)
        __syncthreads();
        if (tx == 0) {
            __threadfence();
            unsigned arrived = atomicAdd(&g_count[dir], 1u);
            if (arrived == 64u * (unsigned)(s + 1) - 1u) {
                __threadfence();
                g_release[dir] = (unsigned)(s + 1);
            } else {
                while (g_release[dir] < (unsigned)(s + 1)) __nanosleep(20);
            }
            __threadfence();
        }
        __syncthreads();

        if (s < 511) {
            const float* hsrc = hout + (size_t)(t * 128 + b0) * 256;
            for (int i = tx; i < 4096; i += 256) sH[i] = hsrc[i];
            __syncthreads();
        }
    }
}

// ---------------- feats = concat(hf,hb) @ Wo^T + bo ----------------
#define FEATS_SMEM (512 * 32 * 4)
__global__ void __launch_bounds__(256) feats_kernel(const float* __restrict__ bo)
{
    extern __shared__ float sWo[];  // [512][32]: sWo[k*32 + l]
    const int tx = threadIdx.x;
    for (int i = tx; i < 512 * 32; i += 256) sWo[i] = g_WoT[i];
    __syncthreads();

    const int w = tx >> 5, l = tx & 31;
    const int m0 = blockIdx.x * 64 + w * 8;
    const float bias = bo[l];

#pragma unroll 1
    for (int r = 0; r < 8; r++) {
        const int m = m0 + r;
        const float* hf = &g_hf[(size_t)m * 256];
        const float* hb = &g_hb[(size_t)m * 256];
        float acc = bias;
#pragma unroll 4
        for (int k = 0; k < 256; k += 4) {
            float4 h4 = *(const float4*)(hf + k);
            acc = fmaf(h4.x, sWo[(k + 0) * 32 + l], acc);
            acc = fmaf(h4.y, sWo[(k + 1) * 32 + l], acc);
            acc = fmaf(h4.z, sWo[(k + 2) * 32 + l], acc);
            acc = fmaf(h4.w, sWo[(k + 3) * 32 + l], acc);
        }
#pragma unroll 4
        for (int k = 0; k < 256; k += 4) {
            float4 h4 = *(const float4*)(hb + k);
            acc = fmaf(h4.x, sWo[(256 + k + 0) * 32 + l], acc);
            acc = fmaf(h4.y, sWo[(256 + k + 1) * 32 + l], acc);
            acc = fmaf(h4.z, sWo[(256 + k + 2) * 32 + l], acc);
            acc = fmaf(h4.w, sWo[(256 + k + 3) * 32 + l], acc);
        }
        g_feats[(size_t)m * 32 + l] = acc;
    }
}

// ---------------- CRF forward (log-partition): one warp per batch elem ----------------
__global__ void __launch_bounds__(32) crf_fwd_kernel(const float* __restrict__ trans)
{
    const int b = blockIdx.x;
    const int l = threadIdx.x;  // destination tag

    float tr[32];
#pragma unroll
    for (int i = 0; i < 32; i++) tr[i] = trans[i * 32 + l];  // trans[i][l]

    float dp = (l == START_TAG) ? 0.0f : NEGV;

    for (int t = 0; t < 512; t++) {
        float sc = g_feats[(size_t)(t * 128 + b) * 32 + l];
        float v[32];
        float m = -3.0e38f;
#pragma unroll
        for (int i = 0; i < 32; i++) {
            v[i] = __shfl_sync(0xffffffffu, dp, i) + tr[i];
            m = fmaxf(m, v[i]);
        }
        float ssum = 0.0f;
#pragma unroll
        for (int i = 0; i < 32; i++) ssum += __expf(v[i] - m);
        dp = m + __logf(ssum) + sc;
    }

    // logsumexp over lanes
    float m = dp;
#pragma unroll
    for (int o = 16; o; o >>= 1) m = fmaxf(m, __shfl_xor_sync(0xffffffffu, m, o));
    float e = __expf(dp - m);
#pragma unroll
    for (int o = 16; o; o >>= 1) e += __shfl_xor_sync(0xffffffffu, e, o);
    if (l == 0) g_Z[b] = m + __logf(e);
}

// ---------------- gold path score ----------------
__global__ void __launch_bounds__(128) gold_kernel(
    const int* __restrict__ labels, const float* __restrict__ trans)
{
    const int b = threadIdx.x;
    float g = 0.0f;
    int lp = START_TAG;
#pragma unroll 4
    for (int t = 0; t < 512; t++) {
        int ln = labels[t * 128 + b];
        g += trans[lp * 32 + ln] + g_feats[(size_t)(t * 128 + b) * 32 + ln];
        lp = ln;
    }
    g_gold[b] = g;
}

// ---------------- final reduce ----------------
__global__ void __launch_bounds__(128) final_kernel(float* __restrict__ out)
{
    __shared__ float red[128];
    const int b = threadIdx.x;
    red[b] = g_Z[b] - g_gold[b];
    __syncthreads();
    for (int o = 64; o; o >>= 1) {
        if (b < o) red[b] += red[b + o];
        __syncthreads();
    }
    if (b == 0) out[0] = red[0] / 128.0f;
}

// ---------------- launch ----------------
extern "C" void kernel_launch(void* const* d_in, const int* in_sizes, int n_in,
                              void* d_out, int out_size)
{
    (void)in_sizes; (void)n_in; (void)out_size;
    const float* emb    = (const float*)d_in[0];
    const float* W_ih_f = (const float*)d_in[1];
    const float* W_hh_f = (const float*)d_in[2];
    const float* b_f    = (const float*)d_in[3];
    const float* W_ih_b = (const float*)d_in[4];
    const float* W_hh_b = (const float*)d_in[5];
    const float* b_b    = (const float*)d_in[6];
    const float* Wo     = (const float*)d_in[7];
    const float* bo     = (const float*)d_in[8];
    const float* trans  = (const float*)d_in[9];
    const float* h0     = (const float*)d_in[10];
    const float* c0     = (const float*)d_in[11];
    const int*   sent   = (const int*)d_in[12];
    const int*   labels = (const int*)d_in[13];
    float* out = (float*)d_out;

    cudaFuncSetAttribute(lstm_kernel, cudaFuncAttributeMaxDynamicSharedMemorySize, LSTM_SMEM);
    cudaFuncSetAttribute(feats_kernel, cudaFuncAttributeMaxDynamicSharedMemorySize, FEATS_SMEM);

    prep_kernel<<<1, 256>>>(Wo);
    proj_kernel<<<dim3(512, 8, 2), 256>>>(emb, sent, W_ih_f, b_f, W_ih_b, b_b);
    lstm_kernel<<<128, 256, LSTM_SMEM>>>(W_hh_f, W_hh_b, h0, c0);
    feats_kernel<<<1024, 256, FEATS_SMEM>>>(bo);
    crf_fwd_kernel<<<128, 32>>>(trans);
    gold_kernel<<<1, 128>>>(labels, trans);
    final_kernel<<<1, 128>>>(out);
}

// round 3
// speedup vs baseline: 1.9259x; 1.9120x over previous
#include <cuda_runtime.h>
#include <cuda_bf16.h>
#include <cstdint>

#define M_TOT 65536
#define START_TAG 30
#define NEGV  (-10000.0f)

// ---------------- device scratch ----------------
__device__ __nv_bfloat16 g_xemb[(size_t)M_TOT * 256];          // gathered emb, bf16
__device__ __nv_bfloat16 g_wih[2 * 1024 * 256];                // permuted, bf16
__device__ __nv_bfloat16 g_whh[2 * 1024 * 256];                // permuted, bf16
__device__ __nv_bfloat16 g_wo[32 * 512];
__device__ float g_bias[2 * 1024];                             // permuted combined bias
__device__ __nv_bfloat16 g_x[(size_t)2 * M_TOT * 1024];        // [dir][m][n'] 268MB
__device__ __nv_bfloat16 g_h[(size_t)M_TOT * 512];             // [m][dir*256+j] 67MB
__device__ float g_feats[(size_t)M_TOT * 32];
__device__ float g_Z[128];
__device__ float g_gold[128];
__device__ volatile unsigned g_flag[128];

// ---------------- helpers ----------------
__device__ __forceinline__ unsigned sptr(const void* p) {
    return (unsigned)__cvta_generic_to_shared(p);
}
__device__ __forceinline__ void ldsm4(unsigned* r, unsigned addr) {
    asm volatile("ldmatrix.sync.aligned.m8n8.x4.shared.b16 {%0,%1,%2,%3},[%4];"
                 : "=r"(r[0]), "=r"(r[1]), "=r"(r[2]), "=r"(r[3]) : "r"(addr));
}
__device__ __forceinline__ void mma16816(float* d, const unsigned* a, const unsigned* b) {
    asm volatile("mma.sync.aligned.m16n8k16.row.col.f32.bf16.bf16.f32 "
                 "{%0,%1,%2,%3},{%4,%5,%6,%7},{%8,%9},{%0,%1,%2,%3};"
                 : "+f"(d[0]), "+f"(d[1]), "+f"(d[2]), "+f"(d[3])
                 : "r"(a[0]), "r"(a[1]), "r"(a[2]), "r"(a[3]), "r"(b[0]), "r"(b[1]));
}
__device__ __forceinline__ unsigned packbf(float a, float b) {
    __nv_bfloat162 t = __float22bfloat162_rn(make_float2(a, b));
    return *(unsigned*)&t;
}
__device__ __forceinline__ float lo16(unsigned u) { return __uint_as_float(u << 16); }
__device__ __forceinline__ float hi16(unsigned u) { return __uint_as_float(u & 0xffff0000u); }
__device__ __forceinline__ float tanha(float x) {
    float y; asm("tanh.approx.f32 %0, %1;" : "=f"(y) : "f"(x)); return y;
}
__device__ __forceinline__ float sigax(float x) {
    return fmaf(tanha(x * 0.5f), 0.5f, 0.5f);
}

// ---------------- prep: convert+permute weights, biases, reset flags ----------------
// permutation: stored row n' corresponds to original W row perm(n') = (n'&3)*256 + (n'>>2)
__global__ void prep_misc(const float* __restrict__ Wf, const float* __restrict__ Whf,
                          const float* __restrict__ bf, const float* __restrict__ Wb,
                          const float* __restrict__ Whb, const float* __restrict__ bb,
                          const float* __restrict__ Wo)
{
    int idx = blockIdx.x * blockDim.x + threadIdx.x;
    int stride = gridDim.x * blockDim.x;
    for (int i = idx; i < 2 * 1024 * 256; i += stride) {
        int dir = i >> 18;
        int r = (i >> 8) & 1023;
        int k = i & 255;
        int pr = (r & 3) * 256 + (r >> 2);
        const float* Wi = dir ? Wb : Wf;
        const float* Wh = dir ? Whb : Whf;
        g_wih[i] = __float2bfloat16(Wi[pr * 256 + k]);
        g_whh[i] = __float2bfloat16(Wh[pr * 256 + k]);
    }
    for (int i = idx; i < 32 * 512; i += stride) g_wo[i] = __float2bfloat16(Wo[i]);
    for (int i = idx; i < 2048; i += stride) {
        int dir = i >> 10;
        int r = i & 1023;
        int pr = (r & 3) * 256 + (r >> 2);
        g_bias[i] = (dir ? bb : bf)[pr];
    }
    for (int i = idx; i < 128; i += stride) g_flag[i] = 0;
}

// ---------------- gather emb[sent] -> bf16 ----------------
__global__ void __launch_bounds__(256) gather_k(const float* __restrict__ emb,
                                                const int* __restrict__ sent)
{
    int m = blockIdx.x * 8 + (threadIdx.x >> 5);
    int lane = threadIdx.x & 31;
    int tok = sent[m];
    const float4* src = (const float4*)(emb + (size_t)tok * 256) + lane * 2;
    float4 a = src[0], b = src[1];
    unsigned u0 = packbf(a.x, a.y), u1 = packbf(a.z, a.w);
    unsigned u2 = packbf(b.x, b.y), u3 = packbf(b.z, b.w);
    uint4 v = make_uint4(u0, u1, u2, u3);
    *(uint4*)(g_xemb + (size_t)m * 256 + lane * 8) = v;
}

// ---------------- input projection GEMM (bf16 mma) ----------------
// C[m][n'] = Xemb[m][k] * g_wih[dir][n'][k] + g_bias[dir][n'] ; output bf16 in g_x
// CTA 128x128, k chunks of 64. 8 warps = 4(m) x 2(n): warp tile 32x64.
#define PJS 72
__global__ void __launch_bounds__(256) proj_k()
{
    __shared__ __nv_bfloat16 sA[128 * PJS];
    __shared__ __nv_bfloat16 sB[128 * PJS];
    const int tx = threadIdx.x;
    const int w = tx >> 5, lane = tx & 31;
    const int nt = blockIdx.x, mt = blockIdx.y, dir = blockIdx.z;
    const size_t m0 = (size_t)mt * 128;
    const int n0 = nt * 128;
    const int moff = (w & 3) * 32, noff = (w >> 2) * 64;

    float acc[2][8][4];
#pragma unroll
    for (int a = 0; a < 2; a++)
#pragma unroll
        for (int b = 0; b < 8; b++)
#pragma unroll
            for (int c = 0; c < 4; c++) acc[a][b][c] = 0.0f;

    const int lrow = tx >> 3, lcol = (tx & 7) * 8;
    const __nv_bfloat16* gA = g_xemb + (m0 + lrow) * 256 + lcol;
    const __nv_bfloat16* gB = g_wih + ((size_t)dir * 1024 + n0 + lrow) * 256 + lcol;

    uint4 ra[4], rb[4];
#pragma unroll
    for (int s = 0; s < 4; s++) {
        ra[s] = *(const uint4*)(gA + s * 32 * 256);
        rb[s] = *(const uint4*)(gB + s * 32 * 256);
    }

    const unsigned aAddrBase = sptr(sA) + (((moff + (lane & 15)) * PJS + (lane >> 4) * 8) << 1);
    const int brow = noff + ((lane >> 3) >> 1) * 8 + (lane & 7) + (((lane >> 3) & 0)); // temp
    const int bg = lane >> 3;
    const unsigned bAddrBase = sptr(sB) + (((noff + (bg >> 1) * 8 + (lane & 7)) * PJS + (bg & 1) * 8) << 1);
    (void)brow;

    for (int kc = 0; kc < 4; kc++) {
        __syncthreads();
#pragma unroll
        for (int s = 0; s < 4; s++) {
            *(uint4*)&sA[(lrow + s * 32) * PJS + lcol] = ra[s];
            *(uint4*)&sB[(lrow + s * 32) * PJS + lcol] = rb[s];
        }
        __syncthreads();
        if (kc < 3) {
#pragma unroll
            for (int s = 0; s < 4; s++) {
                ra[s] = *(const uint4*)(gA + s * 32 * 256 + (kc + 1) * 64);
                rb[s] = *(const uint4*)(gB + s * 32 * 256 + (kc + 1) * 64);
            }
        }
#pragma unroll
        for (int kf = 0; kf < 4; kf++) {
            unsigned af[2][4];
            ldsm4(af[0], aAddrBase + kf * 32);
            ldsm4(af[1], aAddrBase + (16 * PJS * 2) + kf * 32);
#pragma unroll
            for (int p = 0; p < 4; p++) {
                unsigned b4[4];
                ldsm4(b4, bAddrBase + (p * 16 * PJS * 2) + kf * 32);
#pragma unroll
                for (int mf = 0; mf < 2; mf++) {
                    mma16816(acc[mf][2 * p + 0], af[mf], &b4[0]);
                    mma16816(acc[mf][2 * p + 1], af[mf], &b4[2]);
                }
            }
        }
    }

    // epilogue: +bias, -> bf16, store
    __nv_bfloat16* outp = g_x + (size_t)dir * M_TOT * 1024;
#pragma unroll
    for (int nf = 0; nf < 8; nf++) {
        const int ncol = n0 + noff + nf * 8 + (lane & 3) * 2;
        const float b0v = g_bias[dir * 1024 + ncol];
        const float b1v = g_bias[dir * 1024 + ncol + 1];
#pragma unroll
        for (int mf = 0; mf < 2; mf++) {
            const size_t mlo = m0 + moff + mf * 16 + (lane >> 2);
            *(unsigned*)(outp + mlo * 1024 + ncol) =
                packbf(acc[mf][nf][0] + b0v, acc[mf][nf][1] + b1v);
            *(unsigned*)(outp + (mlo + 8) * 1024 + ncol) =
                packbf(acc[mf][nf][2] + b0v, acc[mf][nf][3] + b1v);
        }
    }
}

// ---------------- persistent bi-LSTM (bf16 mma, W_hh in registers) ----------------
__global__ void __launch_bounds__(256) lstm_k(const float* __restrict__ h0,
                                              const float* __restrict__ c0)
{
    __shared__ __nv_bfloat16 sA[16 * 264];
    const int tx = threadIdx.x, w = tx >> 5, lane = tx & 31;
    const int bx = blockIdx.x;
    const int dir = bx >> 6, cid = bx & 63;
    const int b0 = (cid >> 3) << 4;
    const int jt = cid & 7;
    const int N0 = jt << 7;
    const int j0 = jt << 5;

    // --- load W_hh fragments into registers (resident all 512 steps) ---
    unsigned bw[16][2][2];
    {
        const int row = N0 + w * 16 + (lane >> 2);
        const __nv_bfloat16* base = g_whh + (size_t)dir * 1024 * 256;
#pragma unroll
        for (int kf = 0; kf < 16; kf++) {
#pragma unroll
            for (int nf = 0; nf < 2; nf++) {
                const __nv_bfloat16* rp =
                    base + (size_t)(row + nf * 8) * 256 + kf * 16 + (lane & 3) * 2;
                bw[kf][nf][0] = *(const unsigned*)rp;
                bw[kf][nf][1] = *(const unsigned*)(rp + 8);
            }
        }
    }

    const bool owner = ((lane & 1) == 0);
    const int r = lane >> 2;
    const int jjb = j0 + w * 4 + ((lane & 3) >> 1);

    float cs[4];
#pragma unroll
    for (int nf = 0; nf < 2; nf++)
#pragma unroll
        for (int h = 0; h < 2; h++)
            cs[nf * 2 + h] = owner
                ? c0[(size_t)(dir * 128 + b0 + r + h * 8) * 256 + jjb + nf * 2]
                : 0.0f;

    // --- init sA from h0 (fp32 -> bf16) ---
    {
        const int row = tx >> 4, seg = tx & 15;
        const float* hp = h0 + (size_t)(dir * 128 + b0 + row) * 256 + seg * 16;
        float4 f0 = *(const float4*)(hp + 0), f1 = *(const float4*)(hp + 4);
        float4 f2 = *(const float4*)(hp + 8), f3 = *(const float4*)(hp + 12);
        uint4 v0 = make_uint4(packbf(f0.x, f0.y), packbf(f0.z, f0.w),
                              packbf(f1.x, f1.y), packbf(f1.z, f1.w));
        uint4 v1 = make_uint4(packbf(f2.x, f2.y), packbf(f2.z, f2.w),
                              packbf(f3.x, f3.y), packbf(f3.z, f3.w));
        *(uint4*)&sA[row * 264 + seg * 16 + 0] = v0;
        *(uint4*)&sA[row * 264 + seg * 16 + 8] = v1;
    }
    __syncthreads();

    const unsigned aAddr = sptr(sA) + (((lane & 15) * 264 + (lane >> 4) * 8) << 1);
    const __nv_bfloat16* xbase = g_x + (size_t)dir * M_TOT * 1024;
    const int xcol = N0 + w * 16 + (lane & 3) * 2;

    // x prefetch for s=0
    unsigned xp[2][2];
    {
        const int t = dir ? 511 : 0;
#pragma unroll
        for (int nf = 0; nf < 2; nf++)
#pragma unroll
            for (int h = 0; h < 2; h++)
                xp[nf][h] = *(const unsigned*)(xbase +
                    (size_t)(t * 128 + b0 + r + h * 8) * 1024 + xcol + nf * 8);
    }

    for (int s = 0; s < 512; s++) {
        const int t = dir ? (511 - s) : s;

        float acc0[2][4], acc1[2][4];
#pragma unroll
        for (int nf = 0; nf < 2; nf++) {
            acc0[nf][0] = lo16(xp[nf][0]); acc0[nf][1] = hi16(xp[nf][0]);
            acc0[nf][2] = lo16(xp[nf][1]); acc0[nf][3] = hi16(xp[nf][1]);
            acc1[nf][0] = acc1[nf][1] = acc1[nf][2] = acc1[nf][3] = 0.0f;
        }
        if (s < 511) {
            const int tn = dir ? (510 - s) : (s + 1);
#pragma unroll
            for (int nf = 0; nf < 2; nf++)
#pragma unroll
                for (int h = 0; h < 2; h++)
                    xp[nf][h] = *(const unsigned*)(xbase +
                        (size_t)(tn * 128 + b0 + r + h * 8) * 1024 + xcol + nf * 8);
        }

#pragma unroll
        for (int kf = 0; kf < 16; kf += 2) {
            unsigned af[4], af2[4];
            ldsm4(af, aAddr + kf * 32);
            mma16816(acc0[0], af, bw[kf][0]);
            mma16816(acc0[1], af, bw[kf][1]);
            ldsm4(af2, aAddr + kf * 32 + 32);
            mma16816(acc1[0], af2, bw[kf + 1][0]);
            mma16816(acc1[1], af2, bw[kf + 1][1]);
        }

        // gates + cell update (owner lanes own cells; shfl brings g,o from partner)
#pragma unroll
        for (int nf = 0; nf < 2; nf++) {
#pragma unroll
            for (int h = 0; h < 2; h++) {
                float p0 = acc0[nf][h * 2 + 0] + acc1[nf][h * 2 + 0];
                float p1 = acc0[nf][h * 2 + 1] + acc1[nf][h * 2 + 1];
                float q0 = __shfl_xor_sync(0xffffffffu, p0, 1);
                float q1 = __shfl_xor_sync(0xffffffffu, p1, 1);
                if (owner) {
                    float ig = sigax(p0), fg = sigax(p1);
                    float gg = tanha(q0), og = sigax(q1);
                    float c = fmaf(fg, cs[nf * 2 + h], ig * gg);
                    cs[nf * 2 + h] = c;
                    float hv = og * tanha(c);
                    g_h[(size_t)(t * 128 + b0 + r + h * 8) * 512 + dir * 256 + jjb + nf * 2] =
                        __float2bfloat16_rn(hv);
                }
            }
        }

        // --- flag-array grid barrier (per direction) ---
        __threadfence();
        __syncthreads();
        if (tx == 0) g_flag[dir * 64 + cid] = (unsigned)(s + 1);
        if (tx < 64) {
            while (g_flag[dir * 64 + tx] < (unsigned)(s + 1)) { }
        }
        __syncthreads();

        if (s < 511) {
            const int row = tx >> 4, seg = tx & 15;
            const __nv_bfloat16* hp =
                g_h + (size_t)(t * 128 + b0 + row) * 512 + dir * 256 + seg * 16;
            uint4 v0 = *(const uint4*)(hp + 0);
            uint4 v1 = *(const uint4*)(hp + 8);
            *(uint4*)&sA[row * 264 + seg * 16 + 0] = v0;
            *(uint4*)&sA[row * 264 + seg * 16 + 8] = v1;
            __syncthreads();
        }
    }
}

// ---------------- feats = g_h @ Wo^T + bo  (bf16 mma) ----------------
#define FAS 40
__global__ void __launch_bounds__(256) feats_k(const float* __restrict__ bo)
{
    __shared__ __nv_bfloat16 sB[32 * 520];
    __shared__ __nv_bfloat16 sA[128 * FAS];
    const int tx = threadIdx.x, w = tx >> 5, lane = tx & 31;
    const size_t m0 = (size_t)blockIdx.x * 128;
    const int moff = w * 16;

    for (int i = tx * 8; i < 16384; i += 2048) {
        int row = i >> 9, k = i & 511;
        *(uint4*)&sB[row * 520 + k] = *(const uint4*)&g_wo[i];
    }

    float acc[4][4];
#pragma unroll
    for (int a = 0; a < 4; a++)
#pragma unroll
        for (int b = 0; b < 4; b++) acc[a][b] = 0.0f;

    const int lrow = tx >> 2, lcol = (tx & 3) * 8;
    const __nv_bfloat16* gA = g_h + (m0 + lrow) * 512 + lcol;
    uint4 ra[2];
    ra[0] = *(const uint4*)(gA);
    ra[1] = *(const uint4*)(gA + 64 * 512);

    const unsigned aAddrBase = sptr(sA) + (((moff + (lane & 15)) * FAS + (lane >> 4) * 8) << 1);
    const int bg = lane >> 3;
    const unsigned bAddrBase = sptr(sB) + ((((bg >> 1) * 8 + (lane & 7)) * 520 + (bg & 1) * 8) << 1);

    for (int kc = 0; kc < 16; kc++) {
        __syncthreads();
        *(uint4*)&sA[lrow * FAS + lcol] = ra[0];
        *(uint4*)&sA[(lrow + 64) * FAS + lcol] = ra[1];
        __syncthreads();
        if (kc < 15) {
            ra[0] = *(const uint4*)(gA + (kc + 1) * 32);
            ra[1] = *(const uint4*)(gA + 64 * 512 + (kc + 1) * 32);
        }
#pragma unroll
        for (int kf = 0; kf < 2; kf++) {
            unsigned af[4];
            ldsm4(af, aAddrBase + kf * 32);
#pragma unroll
            for (int p = 0; p < 2; p++) {
                unsigned b4[4];
                ldsm4(b4, bAddrBase + (p * 16 * 520 * 2) + kc * 64 + kf * 32);
                mma16816(acc[2 * p + 0], af, &b4[0]);
                mma16816(acc[2 * p + 1], af, &b4[2]);
            }
        }
    }

#pragma unroll
    for (int nf = 0; nf < 4; nf++) {
        const int l = nf * 8 + (lane & 3) * 2;
        const float b0v = bo[l], b1v = bo[l + 1];
        const size_t mlo = m0 + moff + (lane >> 2);
        float2 v0 = make_float2(acc[nf][0] + b0v, acc[nf][1] + b1v);
        float2 v1 = make_float2(acc[nf][2] + b0v, acc[nf][3] + b1v);
        *(float2*)&g_feats[mlo * 32 + l] = v0;
        *(float2*)&g_feats[(mlo + 8) * 32 + l] = v1;
    }
}

// ---------------- CRF forward (log-partition): one warp per batch elem ----------------
__global__ void __launch_bounds__(32) crf_fwd_kernel(const float* __restrict__ trans)
{
    const int b = blockIdx.x;
    const int l = threadIdx.x;

    float tr[32];
#pragma unroll
    for (int i = 0; i < 32; i++) tr[i] = trans[i * 32 + l];

    float dp = (l == START_TAG) ? 0.0f : NEGV;

    for (int t = 0; t < 512; t++) {
        float sc = g_feats[(size_t)(t * 128 + b) * 32 + l];
        float v[32];
        float m = -3.0e38f;
#pragma unroll
        for (int i = 0; i < 32; i++) {
            v[i] = __shfl_sync(0xffffffffu, dp, i) + tr[i];
            m = fmaxf(m, v[i]);
        }
        float ssum = 0.0f;
#pragma unroll
        for (int i = 0; i < 32; i++) ssum += __expf(v[i] - m);
        dp = m + __logf(ssum) + sc;
    }

    float m = dp;
#pragma unroll
    for (int o = 16; o; o >>= 1) m = fmaxf(m, __shfl_xor_sync(0xffffffffu, m, o));
    float e = __expf(dp - m);
#pragma unroll
    for (int o = 16; o; o >>= 1) e += __shfl_xor_sync(0xffffffffu, e, o);
    if (l == 0) g_Z[b] = m + __logf(e);
}

// ---------------- gold path score: parallel over t, block per batch ----------------
__global__ void __launch_bounds__(256) gold_k(const int* __restrict__ labels,
                                              const float* __restrict__ trans)
{
    __shared__ float red[256];
    const int b = blockIdx.x, tx = threadIdx.x;
    float s = 0.0f;
    for (int t = tx; t < 512; t += 256) {
        int ln = labels[t * 128 + b];
        int lp = t ? labels[(t - 1) * 128 + b] : START_TAG;
        s += trans[lp * 32 + ln] + g_feats[(size_t)(t * 128 + b) * 32 + ln];
    }
    red[tx] = s;
    __syncthreads();
    for (int o = 128; o; o >>= 1) {
        if (tx < o) red[tx] += red[tx + o];
        __syncthreads();
    }
    if (tx == 0) g_gold[b] = red[0];
}

// ---------------- final reduce ----------------
__global__ void __launch_bounds__(128) final_kernel(float* __restrict__ out)
{
    __shared__ float red[128];
    const int b = threadIdx.x;
    red[b] = g_Z[b] - g_gold[b];
    __syncthreads();
    for (int o = 64; o; o >>= 1) {
        if (b < o) red[b] += red[b + o];
        __syncthreads();
    }
    if (b == 0) out[0] = red[0] / 128.0f;
}

// ---------------- launch ----------------
extern "C" void kernel_launch(void* const* d_in, const int* in_sizes, int n_in,
                              void* d_out, int out_size)
{
    (void)in_sizes; (void)n_in; (void)out_size;
    const float* emb    = (const float*)d_in[0];
    const float* W_ih_f = (const float*)d_in[1];
    const float* W_hh_f = (const float*)d_in[2];
    const float* b_f    = (const float*)d_in[3];
    const float* W_ih_b = (const float*)d_in[4];
    const float* W_hh_b = (const float*)d_in[5];
    const float* b_b    = (const float*)d_in[6];
    const float* Wo     = (const float*)d_in[7];
    const float* bo     = (const float*)d_in[8];
    const float* trans  = (const float*)d_in[9];
    const float* h0     = (const float*)d_in[10];
    const float* c0     = (const float*)d_in[11];
    const int*   sent   = (const int*)d_in[12];
    const int*   labels = (const int*)d_in[13];
    float* out = (float*)d_out;

    prep_misc<<<512, 256>>>(W_ih_f, W_hh_f, b_f, W_ih_b, W_hh_b, b_b, Wo);
    gather_k<<<8192, 256>>>(emb, sent);
    proj_k<<<dim3(8, 512, 2), 256>>>();
    lstm_k<<<128, 256>>>(h0, c0);
    feats_k<<<512, 256>>>(bo);
    crf_fwd_kernel<<<128, 32>>>(trans);
    gold_k<<<128, 256>>>(labels, trans);
    final_kernel<<<1, 128>>>(out);
}

// round 4
// speedup vs baseline: 4.1378x; 2.1485x over previous
#include <cuda_runtime.h>
#include <cuda_bf16.h>
#include <cstdint>

#define M_TOT 65536
#define START_TAG 30
#define NEGV  (-10000.0f)

// ---------------- device scratch ----------------
__device__ __nv_bfloat16 g_xemb[(size_t)M_TOT * 256];          // gathered emb, bf16
__device__ __nv_bfloat16 g_wih[2 * 1024 * 256];                // permuted, bf16
__device__ __nv_bfloat16 g_whh[2 * 1024 * 256];                // permuted, bf16
__device__ __nv_bfloat16 g_wo[32 * 512];
__device__ float g_bias[2 * 1024];                             // permuted combined bias
__device__ __nv_bfloat16 g_x[(size_t)2 * M_TOT * 1024];        // [dir][m][n'] 268MB
__device__ __nv_bfloat16 g_h[(size_t)M_TOT * 512];             // [m][dir*256+j] 67MB
__device__ float g_feats[(size_t)M_TOT * 32];
__device__ float g_Z[128];
__device__ float g_gold[128];

// ---------------- helpers ----------------
__device__ __forceinline__ unsigned sptr(const void* p) {
    return (unsigned)__cvta_generic_to_shared(p);
}
__device__ __forceinline__ void ldsm4(unsigned* r, unsigned addr) {
    asm volatile("ldmatrix.sync.aligned.m8n8.x4.shared.b16 {%0,%1,%2,%3},[%4];"
                 : "=r"(r[0]), "=r"(r[1]), "=r"(r[2]), "=r"(r[3]) : "r"(addr));
}
__device__ __forceinline__ void mma16816(float* d, const unsigned* a, const unsigned* b) {
    asm volatile("mma.sync.aligned.m16n8k16.row.col.f32.bf16.bf16.f32 "
                 "{%0,%1,%2,%3},{%4,%5,%6,%7},{%8,%9},{%0,%1,%2,%3};"
                 : "+f"(d[0]), "+f"(d[1]), "+f"(d[2]), "+f"(d[3])
                 : "r"(a[0]), "r"(a[1]), "r"(a[2]), "r"(a[3]), "r"(b[0]), "r"(b[1]));
}
__device__ __forceinline__ unsigned packbf(float a, float b) {
    __nv_bfloat162 t = __float22bfloat162_rn(make_float2(a, b));
    return *(unsigned*)&t;
}
__device__ __forceinline__ float lo16(unsigned u) { return __uint_as_float(u << 16); }
__device__ __forceinline__ float hi16(unsigned u) { return __uint_as_float(u & 0xffff0000u); }
__device__ __forceinline__ float tanha(float x) {
    float y; asm("tanh.approx.f32 %0, %1;" : "=f"(y) : "f"(x)); return y;
}
__device__ __forceinline__ float sigax(float x) {
    return fmaf(tanha(x * 0.5f), 0.5f, 0.5f);
}

// ---------------- prep: convert+permute weights, biases ----------------
// permutation: stored row n' corresponds to original W row perm(n') = (n'&3)*256 + (n'>>2)
__global__ void prep_misc(const float* __restrict__ Wf, const float* __restrict__ Whf,
                          const float* __restrict__ bf, const float* __restrict__ Wb,
                          const float* __restrict__ Whb, const float* __restrict__ bb,
                          const float* __restrict__ Wo)
{
    int idx = blockIdx.x * blockDim.x + threadIdx.x;
    int stride = gridDim.x * blockDim.x;
    for (int i = idx; i < 2 * 1024 * 256; i += stride) {
        int dir = i >> 18;
        int r = (i >> 8) & 1023;
        int k = i & 255;
        int pr = (r & 3) * 256 + (r >> 2);
        const float* Wi = dir ? Wb : Wf;
        const float* Wh = dir ? Whb : Whf;
        g_wih[i] = __float2bfloat16(Wi[pr * 256 + k]);
        g_whh[i] = __float2bfloat16(Wh[pr * 256 + k]);
    }
    for (int i = idx; i < 32 * 512; i += stride) g_wo[i] = __float2bfloat16(Wo[i]);
    for (int i = idx; i < 2048; i += stride) {
        int dir = i >> 10;
        int r = i & 1023;
        int pr = (r & 3) * 256 + (r >> 2);
        g_bias[i] = (dir ? bb : bf)[pr];
    }
}

// ---------------- gather emb[sent] -> bf16 ----------------
__global__ void __launch_bounds__(256) gather_k(const float* __restrict__ emb,
                                                const int* __restrict__ sent)
{
    int m = blockIdx.x * 8 + (threadIdx.x >> 5);
    int lane = threadIdx.x & 31;
    int tok = sent[m];
    const float4* src = (const float4*)(emb + (size_t)tok * 256) + lane * 2;
    float4 a = src[0], b = src[1];
    unsigned u0 = packbf(a.x, a.y), u1 = packbf(a.z, a.w);
    unsigned u2 = packbf(b.x, b.y), u3 = packbf(b.z, b.w);
    uint4 v = make_uint4(u0, u1, u2, u3);
    *(uint4*)(g_xemb + (size_t)m * 256 + lane * 8) = v;
}

// ---------------- input projection GEMM (bf16 mma) ----------------
#define PJS 72
__global__ void __launch_bounds__(256) proj_k()
{
    __shared__ __nv_bfloat16 sA[128 * PJS];
    __shared__ __nv_bfloat16 sB[128 * PJS];
    const int tx = threadIdx.x;
    const int w = tx >> 5, lane = tx & 31;
    const int nt = blockIdx.x, mt = blockIdx.y, dir = blockIdx.z;
    const size_t m0 = (size_t)mt * 128;
    const int n0 = nt * 128;
    const int moff = (w & 3) * 32, noff = (w >> 2) * 64;

    float acc[2][8][4];
#pragma unroll
    for (int a = 0; a < 2; a++)
#pragma unroll
        for (int b = 0; b < 8; b++)
#pragma unroll
            for (int c = 0; c < 4; c++) acc[a][b][c] = 0.0f;

    const int lrow = tx >> 3, lcol = (tx & 7) * 8;
    const __nv_bfloat16* gA = g_xemb + (m0 + lrow) * 256 + lcol;
    const __nv_bfloat16* gB = g_wih + ((size_t)dir * 1024 + n0 + lrow) * 256 + lcol;

    uint4 ra[4], rb[4];
#pragma unroll
    for (int s = 0; s < 4; s++) {
        ra[s] = *(const uint4*)(gA + s * 32 * 256);
        rb[s] = *(const uint4*)(gB + s * 32 * 256);
    }

    const unsigned aAddrBase = sptr(sA) + (((moff + (lane & 15)) * PJS + (lane >> 4) * 8) << 1);
    const int bg = lane >> 3;
    const unsigned bAddrBase = sptr(sB) + (((noff + (bg >> 1) * 8 + (lane & 7)) * PJS + (bg & 1) * 8) << 1);

    for (int kc = 0; kc < 4; kc++) {
        __syncthreads();
#pragma unroll
        for (int s = 0; s < 4; s++) {
            *(uint4*)&sA[(lrow + s * 32) * PJS + lcol] = ra[s];
            *(uint4*)&sB[(lrow + s * 32) * PJS + lcol] = rb[s];
        }
        __syncthreads();
        if (kc < 3) {
#pragma unroll
            for (int s = 0; s < 4; s++) {
                ra[s] = *(const uint4*)(gA + s * 32 * 256 + (kc + 1) * 64);
                rb[s] = *(const uint4*)(gB + s * 32 * 256 + (kc + 1) * 64);
            }
        }
#pragma unroll
        for (int kf = 0; kf < 4; kf++) {
            unsigned af[2][4];
            ldsm4(af[0], aAddrBase + kf * 32);
            ldsm4(af[1], aAddrBase + (16 * PJS * 2) + kf * 32);
#pragma unroll
            for (int p = 0; p < 4; p++) {
                unsigned b4[4];
                ldsm4(b4, bAddrBase + (p * 16 * PJS * 2) + kf * 32);
#pragma unroll
                for (int mf = 0; mf < 2; mf++) {
                    mma16816(acc[mf][2 * p + 0], af[mf], &b4[0]);
                    mma16816(acc[mf][2 * p + 1], af[mf], &b4[2]);
                }
            }
        }
    }

    __nv_bfloat16* outp = g_x + (size_t)dir * M_TOT * 1024;
#pragma unroll
    for (int nf = 0; nf < 8; nf++) {
        const int ncol = n0 + noff + nf * 8 + (lane & 3) * 2;
        const float b0v = g_bias[dir * 1024 + ncol];
        const float b1v = g_bias[dir * 1024 + ncol + 1];
#pragma unroll
        for (int mf = 0; mf < 2; mf++) {
            const size_t mlo = m0 + moff + mf * 16 + (lane >> 2);
            *(unsigned*)(outp + mlo * 1024 + ncol) =
                packbf(acc[mf][nf][0] + b0v, acc[mf][nf][1] + b1v);
            *(unsigned*)(outp + (mlo + 8) * 1024 + ncol) =
                packbf(acc[mf][nf][2] + b0v, acc[mf][nf][3] + b1v);
        }
    }
}

// ---------------- persistent bi-LSTM: cluster of 8 CTAs, DSMEM h exchange ----------------
#define SA_ELEM (16 * 264)
#define SA_BYTES (SA_ELEM * 2)

__global__ void __launch_bounds__(256, 1) __cluster_dims__(8, 1, 1)
lstm_k(const float* __restrict__ h0, const float* __restrict__ c0)
{
    __shared__ __align__(16) __nv_bfloat16 sA[2][SA_ELEM];     // double-buffered h (16 x 256, stride 264)
    __shared__ __align__(16) __nv_bfloat16 sStage[16 * 32];    // my h tile staging
    const int tx = threadIdx.x, w = tx >> 5, lane = tx & 31;
    const int bx = blockIdx.x;
    const int dir = bx >> 6, cid = bx & 63;
    const int b0 = (cid >> 3) << 4;    // batch tile start
    const int jt = bx & 7;             // cluster rank = j tile
    const int N0 = jt << 7;            // n' tile start (128 wide)
    const int j0 = jt << 5;            // j tile start (32 wide)

    // --- W_hh fragments resident in registers ---
    unsigned bw[16][2][2];
    {
        const int row = N0 + w * 16 + (lane >> 2);
        const __nv_bfloat16* base = g_whh + (size_t)dir * 1024 * 256;
#pragma unroll
        for (int kf = 0; kf < 16; kf++) {
#pragma unroll
            for (int nf = 0; nf < 2; nf++) {
                const __nv_bfloat16* rp =
                    base + (size_t)(row + nf * 8) * 256 + kf * 16 + (lane & 3) * 2;
                bw[kf][nf][0] = *(const unsigned*)rp;
                bw[kf][nf][1] = *(const unsigned*)(rp + 8);
            }
        }
    }

    const bool owner = ((lane & 1) == 0);
    const int r = lane >> 2;
    const int jloc = w * 4 + ((lane & 3) >> 1);   // local j col (of 32), +nf*2

    float cs[4];
#pragma unroll
    for (int nf = 0; nf < 2; nf++)
#pragma unroll
        for (int h2 = 0; h2 < 2; h2++)
            cs[nf * 2 + h2] = owner
                ? c0[(size_t)(dir * 128 + b0 + r + h2 * 8) * 256 + j0 + jloc + nf * 2]
                : 0.0f;

    // --- init sA[0] from h0 (fp32 -> bf16), full 16x256 ---
    {
        const int row = tx >> 4, seg = tx & 15;
        const float* hp = h0 + (size_t)(dir * 128 + b0 + row) * 256 + seg * 16;
        float4 f0 = *(const float4*)(hp + 0), f1 = *(const float4*)(hp + 4);
        float4 f2 = *(const float4*)(hp + 8), f3 = *(const float4*)(hp + 12);
        uint4 v0 = make_uint4(packbf(f0.x, f0.y), packbf(f0.z, f0.w),
                              packbf(f1.x, f1.y), packbf(f1.z, f1.w));
        uint4 v1 = make_uint4(packbf(f2.x, f2.y), packbf(f2.z, f2.w),
                              packbf(f3.x, f3.y), packbf(f3.z, f3.w));
        *(uint4*)&sA[0][row * 264 + seg * 16 + 0] = v0;
        *(uint4*)&sA[0][row * 264 + seg * 16 + 8] = v1;
    }
    __syncthreads();

    // --- precompute DSMEM peer addresses for my copy chunk (threads 0..127) ---
    unsigned paddr[8];
    {
        const int row = (tx & 127) >> 3, seg = tx & 7;
        unsigned la = sptr(&sA[0][0]) + (unsigned)((row * 264 + j0 + seg * 4) * 2);
#pragma unroll
        for (int p = 0; p < 8; p++)
            asm("mapa.shared::cluster.u32 %0, %1, %2;" : "=r"(paddr[p]) : "r"(la), "r"(p));
    }

    const unsigned aAddr0 = sptr(&sA[0][0]) + (((lane & 15) * 264 + (lane >> 4) * 8) << 1);
    const __nv_bfloat16* xbase = g_x + (size_t)dir * M_TOT * 1024;
    const int xcol = N0 + w * 16 + (lane & 3) * 2;

    // x prefetch for s=0
    unsigned xp[2][2];
    {
        const int t = dir ? 511 : 0;
#pragma unroll
        for (int nf = 0; nf < 2; nf++)
#pragma unroll
            for (int h2 = 0; h2 < 2; h2++)
                xp[nf][h2] = *(const unsigned*)(xbase +
                    (size_t)(t * 128 + b0 + r + h2 * 8) * 1024 + xcol + nf * 8);
    }

    for (int s = 0; s < 512; s++) {
        const int t = dir ? (511 - s) : s;
        const unsigned cur = (unsigned)(s & 1);

        float acc0[2][4], acc1[2][4];
#pragma unroll
        for (int nf = 0; nf < 2; nf++) {
            acc0[nf][0] = lo16(xp[nf][0]); acc0[nf][1] = hi16(xp[nf][0]);
            acc0[nf][2] = lo16(xp[nf][1]); acc0[nf][3] = hi16(xp[nf][1]);
            acc1[nf][0] = acc1[nf][1] = acc1[nf][2] = acc1[nf][3] = 0.0f;
        }
        // prefetch x for next step (overlaps everything below)
        if (s < 511) {
            const int tn = dir ? (510 - s) : (s + 1);
#pragma unroll
            for (int nf = 0; nf < 2; nf++)
#pragma unroll
                for (int h2 = 0; h2 < 2; h2++)
                    xp[nf][h2] = *(const unsigned*)(xbase +
                        (size_t)(tn * 128 + b0 + r + h2 * 8) * 1024 + xcol + nf * 8);
        }

        const unsigned aAddr = aAddr0 + cur * SA_BYTES;
#pragma unroll
        for (int kf = 0; kf < 16; kf += 2) {
            unsigned af[4], af2[4];
            ldsm4(af, aAddr + kf * 32);
            mma16816(acc0[0], af, bw[kf][0]);
            mma16816(acc0[1], af, bw[kf][1]);
            ldsm4(af2, aAddr + kf * 32 + 32);
            mma16816(acc1[0], af2, bw[kf + 1][0]);
            mma16816(acc1[1], af2, bw[kf + 1][1]);
        }

        // gates (balanced MUFU: even lanes hold i/f pre-acts, odd lanes g/o)
#pragma unroll
        for (int nf = 0; nf < 2; nf++) {
#pragma unroll
            for (int h2 = 0; h2 < 2; h2++) {
                float p0 = acc0[nf][h2 * 2 + 0] + acc1[nf][h2 * 2 + 0];
                float p1 = acc0[nf][h2 * 2 + 1] + acc1[nf][h2 * 2 + 1];
                float x0 = owner ? 0.5f * p0 : p0;
                float t0 = tanha(x0);
                float a0 = owner ? fmaf(t0, 0.5f, 0.5f) : t0;  // even: sig(i); odd: tanh(g)
                float a1 = sigax(p1);                          // even: sig(f); odd: sig(o)
                float gg = __shfl_xor_sync(0xffffffffu, a0, 1);
                float og = __shfl_xor_sync(0xffffffffu, a1, 1);
                if (owner) {
                    float c = fmaf(a1, cs[nf * 2 + h2], a0 * gg);
                    cs[nf * 2 + h2] = c;
                    float hv = og * tanha(c);
                    sStage[(r + h2 * 8) * 32 + jloc + nf * 2] = __float2bfloat16_rn(hv);
                }
            }
        }
        __syncthreads();   // staging complete

        if (tx < 128) {
            const int row = tx >> 3, seg = tx & 7;
            unsigned long long v = *(const unsigned long long*)&sStage[row * 32 + seg * 4];
            // global h for feats (off critical path)
            *(unsigned long long*)(g_h + (size_t)(t * 128 + b0 + row) * 512 +
                                   dir * 256 + j0 + seg * 4) = v;
            if (s < 511) {
                const unsigned woff = (cur ^ 1u) * SA_BYTES;
#pragma unroll
                for (int p = 0; p < 8; p++)
                    asm volatile("st.shared::cluster.b64 [%0], %1;"
                                 :: "r"(paddr[p] + woff), "l"(v) : "memory");
            }
        }

        if (s < 511) {
            asm volatile("barrier.cluster.arrive.aligned;" ::: "memory");
            asm volatile("barrier.cluster.wait.aligned;" ::: "memory");
        }
    }
}

// ---------------- feats = g_h @ Wo^T + bo  (bf16 mma) ----------------
#define FAS 40
__global__ void __launch_bounds__(256) feats_k(const float* __restrict__ bo)
{
    __shared__ __nv_bfloat16 sB[32 * 520];
    __shared__ __nv_bfloat16 sA[128 * FAS];
    const int tx = threadIdx.x, w = tx >> 5, lane = tx & 31;
    const size_t m0 = (size_t)blockIdx.x * 128;
    const int moff = w * 16;

    for (int i = tx * 8; i < 16384; i += 2048) {
        int row = i >> 9, k = i & 511;
        *(uint4*)&sB[row * 520 + k] = *(const uint4*)&g_wo[i];
    }

    float acc[4][4];
#pragma unroll
    for (int a = 0; a < 4; a++)
#pragma unroll
        for (int b = 0; b < 4; b++) acc[a][b] = 0.0f;

    const int lrow = tx >> 2, lcol = (tx & 3) * 8;
    const __nv_bfloat16* gA = g_h + (m0 + lrow) * 512 + lcol;
    uint4 ra[2];
    ra[0] = *(const uint4*)(gA);
    ra[1] = *(const uint4*)(gA + 64 * 512);

    const unsigned aAddrBase = sptr(sA) + (((moff + (lane & 15)) * FAS + (lane >> 4) * 8) << 1);
    const int bg = lane >> 3;
    const unsigned bAddrBase = sptr(sB) + ((((bg >> 1) * 8 + (lane & 7)) * 520 + (bg & 1) * 8) << 1);

    for (int kc = 0; kc < 16; kc++) {
        __syncthreads();
        *(uint4*)&sA[lrow * FAS + lcol] = ra[0];
        *(uint4*)&sA[(lrow + 64) * FAS + lcol] = ra[1];
        __syncthreads();
        if (kc < 15) {
            ra[0] = *(const uint4*)(gA + (kc + 1) * 32);
            ra[1] = *(const uint4*)(gA + 64 * 512 + (kc + 1) * 32);
        }
#pragma unroll
        for (int kf = 0; kf < 2; kf++) {
            unsigned af[4];
            ldsm4(af, aAddrBase + kf * 32);
#pragma unroll
            for (int p = 0; p < 2; p++) {
                unsigned b4[4];
                ldsm4(b4, bAddrBase + (p * 16 * 520 * 2) + kc * 64 + kf * 32);
                mma16816(acc[2 * p + 0], af, &b4[0]);
                mma16816(acc[2 * p + 1], af, &b4[2]);
            }
        }
    }

#pragma unroll
    for (int nf = 0; nf < 4; nf++) {
        const int l = nf * 8 + (lane & 3) * 2;
        const float b0v = bo[l], b1v = bo[l + 1];
        const size_t mlo = m0 + moff + (lane >> 2);
        float2 v0 = make_float2(acc[nf][0] + b0v, acc[nf][1] + b1v);
        float2 v1 = make_float2(acc[nf][2] + b0v, acc[nf][3] + b1v);
        *(float2*)&g_feats[mlo * 32 + l] = v0;
        *(float2*)&g_feats[(mlo + 8) * 32 + l] = v1;
    }
}

// ---------------- CRF forward: one warp per batch elem, tree max + 4-way exp ----------------
__global__ void __launch_bounds__(32) crf_fwd_kernel(const float* __restrict__ trans)
{
    const int b = blockIdx.x;
    const int l = threadIdx.x;

    float tr[32];
#pragma unroll
    for (int i = 0; i < 32; i++) tr[i] = trans[i * 32 + l];

    float dp = (l == START_TAG) ? 0.0f : NEGV;

    for (int t = 0; t < 512; t++) {
        float sc = g_feats[(size_t)(t * 128 + b) * 32 + l];
        float v[32];
#pragma unroll
        for (int i = 0; i < 32; i++)
            v[i] = __shfl_sync(0xffffffffu, dp, i) + tr[i];
        float mm[16];
#pragma unroll
        for (int i = 0; i < 16; i++) mm[i] = fmaxf(v[2 * i], v[2 * i + 1]);
#pragma unroll
        for (int i = 0; i < 8; i++) mm[i] = fmaxf(mm[2 * i], mm[2 * i + 1]);
#pragma unroll
        for (int i = 0; i < 4; i++) mm[i] = fmaxf(mm[2 * i], mm[2 * i + 1]);
        float m = fmaxf(fmaxf(mm[0], mm[1]), fmaxf(mm[2], mm[3]));
        float s0 = 0.0f, s1 = 0.0f, s2 = 0.0f, s3 = 0.0f;
#pragma unroll
        for (int i = 0; i < 8; i++) {
            s0 += __expf(v[i] - m);
            s1 += __expf(v[i + 8] - m);
            s2 += __expf(v[i + 16] - m);
            s3 += __expf(v[i + 24] - m);
        }
        dp = m + __logf((s0 + s1) + (s2 + s3)) + sc;
    }

    float m = dp;
#pragma unroll
    for (int o = 16; o; o >>= 1) m = fmaxf(m, __shfl_xor_sync(0xffffffffu, m, o));
    float e = __expf(dp - m);
#pragma unroll
    for (int o = 16; o; o >>= 1) e += __shfl_xor_sync(0xffffffffu, e, o);
    if (l == 0) g_Z[b] = m + __logf(e);
}

// ---------------- gold path score: parallel over t ----------------
__global__ void __launch_bounds__(256) gold_k(const int* __restrict__ labels,
                                              const float* __restrict__ trans)
{
    __shared__ float red[256];
    const int b = blockIdx.x, tx = threadIdx.x;
    float s = 0.0f;
    for (int t = tx; t < 512; t += 256) {
        int ln = labels[t * 128 + b];
        int lp = t ? labels[(t - 1) * 128 + b] : START_TAG;
        s += trans[lp * 32 + ln] + g_feats[(size_t)(t * 128 + b) * 32 + ln];
    }
    red[tx] = s;
    __syncthreads();
    for (int o = 128; o; o >>= 1) {
        if (tx < o) red[tx] += red[tx + o];
        __syncthreads();
    }
    if (tx == 0) g_gold[b] = red[0];
}

// ---------------- final reduce ----------------
__global__ void __launch_bounds__(128) final_kernel(float* __restrict__ out)
{
    __shared__ float red[128];
    const int b = threadIdx.x;
    red[b] = g_Z[b] - g_gold[b];
    __syncthreads();
    for (int o = 64; o; o >>= 1) {
        if (b < o) red[b] += red[b + o];
        __syncthreads();
    }
    if (b == 0) out[0] = red[0] / 128.0f;
}

// ---------------- launch ----------------
extern "C" void kernel_launch(void* const* d_in, const int* in_sizes, int n_in,
                              void* d_out, int out_size)
{
    (void)in_sizes; (void)n_in; (void)out_size;
    const float* emb    = (const float*)d_in[0];
    const float* W_ih_f = (const float*)d_in[1];
    const float* W_hh_f = (const float*)d_in[2];
    const float* b_f    = (const float*)d_in[3];
    const float* W_ih_b = (const float*)d_in[4];
    const float* W_hh_b = (const float*)d_in[5];
    const float* b_b    = (const float*)d_in[6];
    const float* Wo     = (const float*)d_in[7];
    const float* bo     = (const float*)d_in[8];
    const float* trans  = (const float*)d_in[9];
    const float* h0     = (const float*)d_in[10];
    const float* c0     = (const float*)d_in[11];
    const int*   sent   = (const int*)d_in[12];
    const int*   labels = (const int*)d_in[13];
    float* out = (float*)d_out;

    prep_misc<<<512, 256>>>(W_ih_f, W_hh_f, b_f, W_ih_b, W_hh_b, b_b, Wo);
    gather_k<<<8192, 256>>>(emb, sent);
    proj_k<<<dim3(8, 512, 2), 256>>>();
    lstm_k<<<128, 256>>>(h0, c0);
    feats_k<<<512, 256>>>(bo);
    crf_fwd_kernel<<<128, 32>>>(trans);
    gold_k<<<128, 256>>>(labels, trans);
    final_kernel<<<1, 128>>>(out);
}

// round 6
// speedup vs baseline: 4.2682x; 1.0315x over previous
#include <cuda_runtime.h>
#include <cuda_bf16.h>
#include <cstdint>

#define M_TOT 65536
#define START_TAG 30
#define NEGV  (-10000.0f)

// ---------------- device scratch ----------------
__device__ __nv_bfloat16 g_xemb[(size_t)M_TOT * 256];          // gathered emb, bf16
__device__ __nv_bfloat16 g_wih[2 * 1024 * 256];                // permuted, bf16
__device__ __nv_bfloat16 g_whh[2 * 1024 * 256];                // permuted, bf16
__device__ __nv_bfloat16 g_wo[32 * 512];
__device__ float g_bias[2 * 1024];                             // permuted combined bias
__device__ __nv_bfloat16 g_h[(size_t)M_TOT * 512];             // [m][dir*256+j] 67MB
__device__ float g_feats[(size_t)M_TOT * 32];
__device__ float g_Z[128];
__device__ float g_gold[128];

// ---------------- helpers ----------------
__device__ __forceinline__ unsigned sptr(const void* p) {
    return (unsigned)__cvta_generic_to_shared(p);
}
__device__ __forceinline__ void ldsm4(unsigned* r, unsigned addr) {
    asm volatile("ldmatrix.sync.aligned.m8n8.x4.shared.b16 {%0,%1,%2,%3},[%4];"
                 : "=r"(r[0]), "=r"(r[1]), "=r"(r[2]), "=r"(r[3]) : "r"(addr));
}
__device__ __forceinline__ void mma16816(float* d, const unsigned* a, const unsigned* b) {
    asm volatile("mma.sync.aligned.m16n8k16.row.col.f32.bf16.bf16.f32 "
                 "{%0,%1,%2,%3},{%4,%5,%6,%7},{%8,%9},{%0,%1,%2,%3};"
                 : "+f"(d[0]), "+f"(d[1]), "+f"(d[2]), "+f"(d[3])
                 : "r"(a[0]), "r"(a[1]), "r"(a[2]), "r"(a[3]), "r"(b[0]), "r"(b[1]));
}
__device__ __forceinline__ unsigned packbf(float a, float b) {
    __nv_bfloat162 t = __float22bfloat162_rn(make_float2(a, b));
    return *(unsigned*)&t;
}
__device__ __forceinline__ float tanha(float x) {
    float y; asm("tanh.approx.f32 %0, %1;" : "=f"(y) : "f"(x)); return y;
}
__device__ __forceinline__ float sigax(float x) {
    return fmaf(tanha(x * 0.5f), 0.5f, 0.5f);
}

// ---------------- prep: convert+permute weights, biases ----------------
// stored row n' corresponds to original W row perm(n') = (n'&3)*256 + (n'>>2)
__global__ void prep_misc(const float* __restrict__ Wf, const float* __restrict__ Whf,
                          const float* __restrict__ bf, const float* __restrict__ Wb,
                          const float* __restrict__ Whb, const float* __restrict__ bb,
                          const float* __restrict__ Wo)
{
    int idx = blockIdx.x * blockDim.x + threadIdx.x;
    int stride = gridDim.x * blockDim.x;
    for (int i = idx; i < 2 * 1024 * 256; i += stride) {
        int dir = i >> 18;
        int r = (i >> 8) & 1023;
        int k = i & 255;
        int pr = (r & 3) * 256 + (r >> 2);
        const float* Wi = dir ? Wb : Wf;
        const float* Wh = dir ? Whb : Whf;
        g_wih[i] = __float2bfloat16(Wi[pr * 256 + k]);
        g_whh[i] = __float2bfloat16(Wh[pr * 256 + k]);
    }
    for (int i = idx; i < 32 * 512; i += stride) g_wo[i] = __float2bfloat16(Wo[i]);
    for (int i = idx; i < 2048; i += stride) {
        int dir = i >> 10;
        int r = i & 1023;
        int pr = (r & 3) * 256 + (r >> 2);
        g_bias[i] = (dir ? bb : bf)[pr];
    }
}

// ---------------- gather emb[sent] -> bf16 ----------------
__global__ void __launch_bounds__(256) gather_k(const float* __restrict__ emb,
                                                const int* __restrict__ sent)
{
    int m = blockIdx.x * 8 + (threadIdx.x >> 5);
    int lane = threadIdx.x & 31;
    int tok = sent[m];
    const float4* src = (const float4*)(emb + (size_t)tok * 256) + lane * 2;
    float4 a = src[0], b = src[1];
    uint4 v = make_uint4(packbf(a.x, a.y), packbf(a.z, a.w),
                         packbf(b.x, b.y), packbf(b.z, b.w));
    *(uint4*)(g_xemb + (size_t)m * 256 + lane * 8) = v;
}

// ---------------- persistent bi-LSTM: cluster of 8, fused input projection ----------------
#define SA_ELEM (16 * 264)
#define SA_BYTES (SA_ELEM * 2)

// async-copy one 16x256 bf16 emb tile into sX buffer (all 256 threads)
__device__ __forceinline__ void cp_x_tile(unsigned sbase, const __nv_bfloat16* g, int tx) {
    const int row = tx >> 4, seg = tx & 15;
    unsigned sa = sbase + (unsigned)((row * 264 + seg * 16) << 1);
    const __nv_bfloat16* ga = g + (size_t)row * 256 + seg * 16;
    asm volatile("cp.async.cg.shared.global [%0],[%1],16;" :: "r"(sa), "l"(ga));
    asm volatile("cp.async.cg.shared.global [%0],[%1],16;" :: "r"(sa + 16), "l"(ga + 8));
    asm volatile("cp.async.commit_group;");
}

__global__ void __launch_bounds__(256, 1) __cluster_dims__(8, 1, 1)
lstm_k(const float* __restrict__ h0, const float* __restrict__ c0)
{
    __shared__ __align__(16) __nv_bfloat16 sA[2][SA_ELEM];     // double-buffered h
    __shared__ __align__(16) __nv_bfloat16 sX[2][SA_ELEM];     // double-buffered emb x
    __shared__ __align__(16) __nv_bfloat16 sStage[16 * 32];
    const int tx = threadIdx.x, w = tx >> 5, lane = tx & 31;
    const int bx = blockIdx.x;
    const int dir = bx >> 6, cid = bx & 63;
    const int b0 = (cid >> 3) << 4;    // batch tile start
    const int jt = bx & 7;             // cluster rank = j tile
    const int N0 = jt << 7;            // n' tile start
    const int j0 = jt << 5;            // j tile start

    // --- W_hh and W_ih fragments resident in registers ---
    unsigned bw[16][2][2], bwi[16][2][2];
    {
        const int row = N0 + w * 16 + (lane >> 2);
        const __nv_bfloat16* baseH = g_whh + (size_t)dir * 1024 * 256;
        const __nv_bfloat16* baseI = g_wih + (size_t)dir * 1024 * 256;
#pragma unroll
        for (int kf = 0; kf < 16; kf++) {
#pragma unroll
            for (int nf = 0; nf < 2; nf++) {
                const size_t off = (size_t)(row + nf * 8) * 256 + kf * 16 + (lane & 3) * 2;
                bw[kf][nf][0]  = *(const unsigned*)(baseH + off);
                bw[kf][nf][1]  = *(const unsigned*)(baseH + off + 8);
                bwi[kf][nf][0] = *(const unsigned*)(baseI + off);
                bwi[kf][nf][1] = *(const unsigned*)(baseI + off + 8);
            }
        }
    }

    const bool owner = ((lane & 1) == 0);
    const int r = lane >> 2;
    const int jloc = w * 4 + ((lane & 3) >> 1);
    const int xcol = N0 + w * 16 + (lane & 3) * 2;

    float bb0[2], bb1[2];
#pragma unroll
    for (int nf = 0; nf < 2; nf++) {
        bb0[nf] = g_bias[dir * 1024 + xcol + nf * 8];
        bb1[nf] = g_bias[dir * 1024 + xcol + nf * 8 + 1];
    }

    float cs[4];
#pragma unroll
    for (int nf = 0; nf < 2; nf++)
#pragma unroll
        for (int h2 = 0; h2 < 2; h2++)
            cs[nf * 2 + h2] = owner
                ? c0[(size_t)(dir * 128 + b0 + r + h2 * 8) * 256 + j0 + jloc + nf * 2]
                : 0.0f;

    // --- init sA[0] from h0 ---
    {
        const int row = tx >> 4, seg = tx & 15;
        const float* hp = h0 + (size_t)(dir * 128 + b0 + row) * 256 + seg * 16;
        float4 f0 = *(const float4*)(hp + 0), f1 = *(const float4*)(hp + 4);
        float4 f2 = *(const float4*)(hp + 8), f3 = *(const float4*)(hp + 12);
        uint4 v0 = make_uint4(packbf(f0.x, f0.y), packbf(f0.z, f0.w),
                              packbf(f1.x, f1.y), packbf(f1.z, f1.w));
        uint4 v1 = make_uint4(packbf(f2.x, f2.y), packbf(f2.z, f2.w),
                              packbf(f3.x, f3.y), packbf(f3.z, f3.w));
        *(uint4*)&sA[0][row * 264 + seg * 16 + 0] = v0;
        *(uint4*)&sA[0][row * 264 + seg * 16 + 8] = v1;
    }

    // --- DSMEM peer addresses ---
    unsigned paddr[8];
    {
        const int row = (tx & 127) >> 3, seg = tx & 7;
        unsigned la = sptr(&sA[0][0]) + (unsigned)((row * 264 + j0 + seg * 4) * 2);
#pragma unroll
        for (int p = 0; p < 8; p++)
            asm("mapa.shared::cluster.u32 %0, %1, %2;" : "=r"(paddr[p]) : "r"(la), "r"(p));
    }

    const unsigned aAddr0 = sptr(&sA[0][0]) + (((lane & 15) * 264 + (lane >> 4) * 8) << 1);
    const unsigned aX0    = sptr(&sX[0][0]) + (((lane & 15) * 264 + (lane >> 4) * 8) << 1);

    // --- prologue: stage emb for t(0) -> sX[1], t(1) -> sX[0] ---
    cp_x_tile(sptr(&sX[0][0]) + SA_BYTES,
              g_xemb + (size_t)((dir ? 511 : 0) * 128 + b0) * 256, tx);
    cp_x_tile(sptr(&sX[0][0]),
              g_xemb + (size_t)((dir ? 510 : 1) * 128 + b0) * 256, tx);
    asm volatile("cp.async.wait_group 1;");
    __syncthreads();   // sA[0] + sX[1] visible

    // --- xacc = W_ih * x(t0) + bias (fp32, stays in regs) ---
    float xacc[2][4];
    {
        float a0[2][4], a1[2][4];
#pragma unroll
        for (int nf = 0; nf < 2; nf++) {
            a0[nf][0] = bb0[nf]; a0[nf][1] = bb1[nf];
            a0[nf][2] = bb0[nf]; a0[nf][3] = bb1[nf];
            a1[nf][0] = a1[nf][1] = a1[nf][2] = a1[nf][3] = 0.0f;
        }
        const unsigned aX = aX0 + SA_BYTES;
#pragma unroll
        for (int kf = 0; kf < 16; kf += 2) {
            unsigned af[4], af2[4];
            ldsm4(af, aX + kf * 32);
            mma16816(a0[0], af, bwi[kf][0]);
            mma16816(a0[1], af, bwi[kf][1]);
            ldsm4(af2, aX + kf * 32 + 32);
            mma16816(a1[0], af2, bwi[kf + 1][0]);
            mma16816(a1[1], af2, bwi[kf + 1][1]);
        }
#pragma unroll
        for (int nf = 0; nf < 2; nf++)
#pragma unroll
            for (int i = 0; i < 4; i++) xacc[nf][i] = a0[nf][i] + a1[nf][i];
    }

    for (int s = 0; s < 512; s++) {
        const int t = dir ? (511 - s) : s;
        const unsigned cur = (unsigned)(s & 1);

        // --- h-mma from sA[cur] ---
        float acc0[2][4], acc1[2][4];
#pragma unroll
        for (int nf = 0; nf < 2; nf++)
#pragma unroll
            for (int i = 0; i < 4; i++) { acc0[nf][i] = 0.0f; acc1[nf][i] = 0.0f; }

        const unsigned aAddr = aAddr0 + cur * SA_BYTES;
#pragma unroll
        for (int kf = 0; kf < 16; kf += 2) {
            unsigned af[4], af2[4];
            ldsm4(af, aAddr + kf * 32);
            mma16816(acc0[0], af, bw[kf][0]);
            mma16816(acc0[1], af, bw[kf][1]);
            ldsm4(af2, aAddr + kf * 32 + 32);
            mma16816(acc1[0], af2, bw[kf + 1][0]);
            mma16816(acc1[1], af2, bw[kf + 1][1]);
        }

        // --- gates (balanced MUFU; even lanes i/f, odd lanes g/o) ---
#pragma unroll
        for (int nf = 0; nf < 2; nf++) {
#pragma unroll
            for (int h2 = 0; h2 < 2; h2++) {
                float p0 = acc0[nf][h2 * 2 + 0] + acc1[nf][h2 * 2 + 0] + xacc[nf][h2 * 2 + 0];
                float p1 = acc0[nf][h2 * 2 + 1] + acc1[nf][h2 * 2 + 1] + xacc[nf][h2 * 2 + 1];
                float x0 = owner ? 0.5f * p0 : p0;
                float t0 = tanha(x0);
                float a0 = owner ? fmaf(t0, 0.5f, 0.5f) : t0;
                float a1 = sigax(p1);
                float gg = __shfl_xor_sync(0xffffffffu, a0, 1);
                float og = __shfl_xor_sync(0xffffffffu, a1, 1);
                if (owner) {
                    float c = fmaf(a1, cs[nf * 2 + h2], a0 * gg);
                    cs[nf * 2 + h2] = c;
                    float hv = og * tanha(c);
                    sStage[(r + h2 * 8) * 32 + jloc + nf * 2] = __float2bfloat16_rn(hv);
                }
            }
        }
        __syncthreads();   // staging complete

        if (tx < 128) {
            const int row = tx >> 3, seg = tx & 7;
            unsigned long long v = *(const unsigned long long*)&sStage[row * 32 + seg * 4];
            *(unsigned long long*)(g_h + (size_t)(t * 128 + b0 + row) * 512 +
                                   dir * 256 + j0 + seg * 4) = v;
            if (s < 511) {
                const unsigned woff = (cur ^ 1u) * SA_BYTES;
#pragma unroll
                for (int p = 0; p < 8; p++)
                    asm volatile("st.shared::cluster.b64 [%0], %1;"
                                 :: "r"(paddr[p] + woff), "l"(v) : "memory");
            }
        }

        if (s < 511) {
            asm volatile("barrier.cluster.arrive.aligned;" ::: "memory");

            // --- fused x-projection for step s+1, in the barrier shadow ---
            if (s < 510) {
                const int t2 = dir ? (509 - s) : (s + 2);
                cp_x_tile(sptr(&sX[0][0]) + (cur ^ 1u) * SA_BYTES,
                          g_xemb + (size_t)(t2 * 128 + b0) * 256, tx);
                asm volatile("cp.async.wait_group 1;");
            } else {
                asm volatile("cp.async.wait_group 0;");
            }
            __syncthreads();   // sX[cur] (emb for t(s+1)) visible to all

            float a0[2][4], a1[2][4];
#pragma unroll
            for (int nf = 0; nf < 2; nf++) {
                a0[nf][0] = bb0[nf]; a0[nf][1] = bb1[nf];
                a0[nf][2] = bb0[nf]; a0[nf][3] = bb1[nf];
                a1[nf][0] = a1[nf][1] = a1[nf][2] = a1[nf][3] = 0.0f;
            }
            const unsigned aX = aX0 + cur * SA_BYTES;
#pragma unroll
            for (int kf = 0; kf < 16; kf += 2) {
                unsigned af[4], af2[4];
                ldsm4(af, aX + kf * 32);
                mma16816(a0[0], af, bwi[kf][0]);
                mma16816(a0[1], af, bwi[kf][1]);
                ldsm4(af2, aX + kf * 32 + 32);
                mma16816(a1[0], af2, bwi[kf + 1][0]);
                mma16816(a1[1], af2, bwi[kf + 1][1]);
            }
#pragma unroll
            for (int nf = 0; nf < 2; nf++)
#pragma unroll
                for (int i = 0; i < 4; i++) xacc[nf][i] = a0[nf][i] + a1[nf][i];

            asm volatile("barrier.cluster.wait.aligned;" ::: "memory");
        }
    }
}

// ---------------- feats = g_h @ Wo^T + bo  (bf16 mma) ----------------
#define FAS 40
__global__ void __launch_bounds__(256) feats_k(const float* __restrict__ bo)
{
    __shared__ __nv_bfloat16 sB[32 * 520];
    __shared__ __nv_bfloat16 sA[128 * FAS];
    const int tx = threadIdx.x, w = tx >> 5, lane = tx & 31;
    const size_t m0 = (size_t)blockIdx.x * 128;
    const int moff = w * 16;

    for (int i = tx * 8; i < 16384; i += 2048) {
        int row = i >> 9, k = i & 511;
        *(uint4*)&sB[row * 520 + k] = *(const uint4*)&g_wo[i];
    }

    float acc[4][4];
#pragma unroll
    for (int a = 0; a < 4; a++)
#pragma unroll
        for (int b = 0; b < 4; b++) acc[a][b] = 0.0f;

    const int lrow = tx >> 2, lcol = (tx & 3) * 8;
    const __nv_bfloat16* gA = g_h + (m0 + lrow) * 512 + lcol;
    uint4 ra[2];
    ra[0] = *(const uint4*)(gA);
    ra[1] = *(const uint4*)(gA + 64 * 512);

    const unsigned aAddrBase = sptr(sA) + (((moff + (lane & 15)) * FAS + (lane >> 4) * 8) << 1);
    const int bg = lane >> 3;
    const unsigned bAddrBase = sptr(sB) + ((((bg >> 1) * 8 + (lane & 7)) * 520 + (bg & 1) * 8) << 1);

    for (int kc = 0; kc < 16; kc++) {
        __syncthreads();
        *(uint4*)&sA[lrow * FAS + lcol] = ra[0];
        *(uint4*)&sA[(lrow + 64) * FAS + lcol] = ra[1];
        __syncthreads();
        if (kc < 15) {
            ra[0] = *(const uint4*)(gA + (kc + 1) * 32);
            ra[1] = *(const uint4*)(gA + 64 * 512 + (kc + 1) * 32);
        }
#pragma unroll
        for (int kf = 0; kf < 2; kf++) {
            unsigned af[4];
            ldsm4(af, aAddrBase + kf * 32);
#pragma unroll
            for (int p = 0; p < 2; p++) {
                unsigned b4[4];
                ldsm4(b4, bAddrBase + (p * 16 * 520 * 2) + kc * 64 + kf * 32);
                mma16816(acc[2 * p + 0], af, &b4[0]);
                mma16816(acc[2 * p + 1], af, &b4[2]);
            }
        }
    }

#pragma unroll
    for (int nf = 0; nf < 4; nf++) {
        const int l = nf * 8 + (lane & 3) * 2;
        const float b0v = bo[l], b1v = bo[l + 1];
        const size_t mlo = m0 + moff + (lane >> 2);
        float2 v0 = make_float2(acc[nf][0] + b0v, acc[nf][1] + b1v);
        float2 v1 = make_float2(acc[nf][2] + b0v, acc[nf][3] + b1v);
        *(float2*)&g_feats[mlo * 32 + l] = v0;
        *(float2*)&g_feats[(mlo + 8) * 32 + l] = v1;
    }
}

// ---------------- CRF forward: one warp per batch elem ----------------
__global__ void __launch_bounds__(32) crf_fwd_kernel(const float* __restrict__ trans)
{
    const int b = blockIdx.x;
    const int l = threadIdx.x;

    float tr[32];
#pragma unroll
    for (int i = 0; i < 32; i++) tr[i] = trans[i * 32 + l];

    float dp = (l == START_TAG) ? 0.0f : NEGV;

    for (int t = 0; t < 512; t++) {
        float sc = g_feats[(size_t)(t * 128 + b) * 32 + l];
        float v[32];
#pragma unroll
        for (int i = 0; i < 32; i++)
            v[i] = __shfl_sync(0xffffffffu, dp, i) + tr[i];
        float mm[16];
#pragma unroll
        for (int i = 0; i < 16; i++) mm[i] = fmaxf(v[2 * i], v[2 * i + 1]);
#pragma unroll
        for (int i = 0; i < 8; i++) mm[i] = fmaxf(mm[2 * i], mm[2 * i + 1]);
#pragma unroll
        for (int i = 0; i < 4; i++) mm[i] = fmaxf(mm[2 * i], mm[2 * i + 1]);
        float m = fmaxf(fmaxf(mm[0], mm[1]), fmaxf(mm[2], mm[3]));
        float s0 = 0.0f, s1 = 0.0f, s2 = 0.0f, s3 = 0.0f;
#pragma unroll
        for (int i = 0; i < 8; i++) {
            s0 += __expf(v[i] - m);
            s1 += __expf(v[i + 8] - m);
            s2 += __expf(v[i + 16] - m);
            s3 += __expf(v[i + 24] - m);
        }
        dp = m + __logf((s0 + s1) + (s2 + s3)) + sc;
    }

    float m = dp;
#pragma unroll
    for (int o = 16; o; o >>= 1) m = fmaxf(m, __shfl_xor_sync(0xffffffffu, m, o));
    float e = __expf(dp - m);
#pragma unroll
    for (int o = 16; o; o >>= 1) e += __shfl_xor_sync(0xffffffffu, e, o);
    if (l == 0) g_Z[b] = m + __logf(e);
}

// ---------------- gold path score ----------------
__global__ void __launch_bounds__(256) gold_k(const int* __restrict__ labels,
                                              const float* __restrict__ trans)
{
    __shared__ float red[256];
    const int b = blockIdx.x, tx = threadIdx.x;
    float s = 0.0f;
    for (int t = tx; t < 512; t += 256) {
        int ln = labels[t * 128 + b];
        int lp = t ? labels[(t - 1) * 128 + b] : START_TAG;
        s += trans[lp * 32 + ln] + g_feats[(size_t)(t * 128 + b) * 32 + ln];
    }
    red[tx] = s;
    __syncthreads();
    for (int o = 128; o; o >>= 1) {
        if (tx < o) red[tx] += red[tx + o];
        __syncthreads();
    }
    if (tx == 0) g_gold[b] = red[0];
}

// ---------------- final reduce ----------------
__global__ void __launch_bounds__(128) final_kernel(float* __restrict__ out)
{
    __shared__ float red[128];
    const int b = threadIdx.x;
    red[b] = g_Z[b] - g_gold[b];
    __syncthreads();
    for (int o = 64; o; o >>= 1) {
        if (b < o) red[b] += red[b + o];
        __syncthreads();
    }
    if (b == 0) out[0] = red[0] / 128.0f;
}

// ---------------- launch ----------------
extern "C" void kernel_launch(void* const* d_in, const int* in_sizes, int n_in,
                              void* d_out, int out_size)
{
    (void)in_sizes; (void)n_in; (void)out_size;
    const float* emb    = (const float*)d_in[0];
    const float* W_ih_f = (const float*)d_in[1];
    const float* W_hh_f = (const float*)d_in[2];
    const float* b_f    = (const float*)d_in[3];
    const float* W_ih_b = (const float*)d_in[4];
    const float* W_hh_b = (const float*)d_in[5];
    const float* b_b    = (const float*)d_in[6];
    const float* Wo     = (const float*)d_in[7];
    const float* bo     = (const float*)d_in[8];
    const float* trans  = (const float*)d_in[9];
    const float* h0     = (const float*)d_in[10];
    const float* c0     = (const float*)d_in[11];
    const int*   sent   = (const int*)d_in[12];
    const int*   labels = (const int*)d_in[13];
    float* out = (float*)d_out;

    prep_misc<<<512, 256>>>(W_ih_f, W_hh_f, b_f, W_ih_b, W_hh_b, b_b, Wo);
    gather_k<<<8192, 256>>>(emb, sent);
    lstm_k<<<128, 256>>>(h0, c0);
    feats_k<<<512, 256>>>(bo);
    crf_fwd_kernel<<<128, 32>>>(trans);
    gold_k<<<128, 256>>>(labels, trans);
    final_kernel<<<1, 128>>>(out);
}